// round 2
// baseline (speedup 1.0000x reference)
#include <cuda_runtime.h>
#include <math.h>

#define Hn    2048
#define Tn    512
#define INn   128
#define OUTn  128
#define G3n   6144
#define DSTEP 64
#define DINn  4096

#define NBLK  256
#define NTHR  256
#define WPB   (NTHR / 32)   // 8 warps per block

// ---------------- device scratch (no allocations allowed) ----------------
__device__ float g_enc_gi[Tn * G3n];    // x @ enc_Wih^T + bih
__device__ float g_enc_out[Tn * Hn];    // encoder hidden states
__device__ float g_U[Tn * Hn];          // enc_out @ U_W^T + U_b
__device__ float g_h[2][Hn];            // double-buffered hidden state
__device__ float g_Wd[Hn];
__device__ float g_scores[Tn];
__device__ float g_aw[Tn];
__device__ float g_ctx_part[32 * Hn];   // ctx partial sums (32 t-chunks)
__device__ float g_din[DINn];
__device__ float g_logits[OUTn];
__device__ int   g_idx;                 // prev argmax (-1 => zero input)

// grid barrier state
__device__ unsigned g_bar_cnt;
__device__ volatile unsigned g_bar_gen;

__device__ __forceinline__ void grid_barrier() {
    __syncthreads();
    if (threadIdx.x == 0) {
        unsigned gen = g_bar_gen;
        __threadfence();
        if (atomicAdd(&g_bar_cnt, 1u) == NBLK - 1) {
            g_bar_cnt = 0;
            __threadfence();
            g_bar_gen = gen + 1;
        } else {
            while (g_bar_gen == gen) { }
            __threadfence();
        }
    }
    __syncthreads();
}

__device__ __forceinline__ float sigmoidf_acc(float x) {
    return 1.0f / (1.0f + expf(-x));
}

// ---------------- generic tiled GEMM:  C[M,N] = A[M,K] @ B[N,K]^T + bias[N] ----------------
__global__ void __launch_bounds__(256) gemm_nt_bias(
    const float* __restrict__ A, const float* __restrict__ B,
    const float* __restrict__ bias, float* __restrict__ C,
    int M, int N, int K)
{
    __shared__ float As[16][68];
    __shared__ float Bs[16][68];
    const int m0 = blockIdx.y * 64;
    const int n0 = blockIdx.x * 64;
    const int tid = threadIdx.x;
    const int tx = tid & 15;
    const int ty = tid >> 4;
    float c[4][4] = {};

    for (int k0 = 0; k0 < K; k0 += 16) {
#pragma unroll
        for (int i = 0; i < 4; i++) {
            int idx = tid + i * 256;
            int kk = idx & 15;
            int mm = idx >> 4;
            As[kk][mm] = A[(size_t)(m0 + mm) * K + k0 + kk];
            Bs[kk][mm] = B[(size_t)(n0 + mm) * K + k0 + kk];
        }
        __syncthreads();
#pragma unroll
        for (int kk = 0; kk < 16; kk++) {
            float4 a4 = *(const float4*)&As[kk][ty * 4];
            float4 b4 = *(const float4*)&Bs[kk][tx * 4];
            float av[4] = {a4.x, a4.y, a4.z, a4.w};
            float bv[4] = {b4.x, b4.y, b4.z, b4.w};
#pragma unroll
            for (int i = 0; i < 4; i++)
#pragma unroll
                for (int j = 0; j < 4; j++)
                    c[i][j] = fmaf(av[i], bv[j], c[i][j]);
        }
        __syncthreads();
    }
#pragma unroll
    for (int i = 0; i < 4; i++) {
        int m = m0 + ty * 4 + i;
#pragma unroll
        for (int j = 0; j < 4; j++) {
            int n = n0 + tx * 4 + j;
            C[(size_t)m * N + n] = c[i][j] + bias[n];
        }
    }
}

// ---------------- persistent encoder: 512 GRU steps, grid barrier between ----------------
__global__ void __launch_bounds__(NTHR, 2) enc_persistent(
    const float* __restrict__ Whh, const float* __restrict__ bhh)
{
    const int warp = threadIdx.x >> 5;
    const int lane = threadIdx.x & 31;
    const int j = blockIdx.x * WPB + warp;           // 0..2047
    const int gid = blockIdx.x * NTHR + threadIdx.x;

    if (gid < Hn) g_h[0][gid] = 0.0f;

    const float4* __restrict__ r0 = (const float4*)(Whh + (size_t)j * Hn);
    const float4* __restrict__ r1 = (const float4*)(Whh + (size_t)(Hn + j) * Hn);
    const float4* __restrict__ r2 = (const float4*)(Whh + (size_t)(2 * Hn + j) * Hn);
    const float b0 = bhh[j], b1 = bhh[Hn + j], b2 = bhh[2 * Hn + j];

    grid_barrier();

    for (int t = 0; t < Tn; t++) {
        const float* hin = g_h[t & 1];
        const float4* h4 = (const float4*)hin;
        const float* gi = g_enc_gi + (size_t)t * G3n;
        float gi0 = 0.f, gi1 = 0.f, gi2 = 0.f, hprev = 0.f;
        if (lane == 0) {
            gi0 = __ldg(gi + j);
            gi1 = __ldg(gi + Hn + j);
            gi2 = __ldg(gi + 2 * Hn + j);
            hprev = __ldcg(hin + j);
        }
        float a0 = 0.f, a1 = 0.f, a2 = 0.f;
#pragma unroll 4
        for (int c = 0; c < Hn / 128; c++) {
            float4 hv = __ldcg(h4 + c * 32 + lane);
            float4 w0 = __ldg(r0 + c * 32 + lane);
            float4 w1 = __ldg(r1 + c * 32 + lane);
            float4 w2 = __ldg(r2 + c * 32 + lane);
            a0 = fmaf(w0.x, hv.x, a0); a0 = fmaf(w0.y, hv.y, a0);
            a0 = fmaf(w0.z, hv.z, a0); a0 = fmaf(w0.w, hv.w, a0);
            a1 = fmaf(w1.x, hv.x, a1); a1 = fmaf(w1.y, hv.y, a1);
            a1 = fmaf(w1.z, hv.z, a1); a1 = fmaf(w1.w, hv.w, a1);
            a2 = fmaf(w2.x, hv.x, a2); a2 = fmaf(w2.y, hv.y, a2);
            a2 = fmaf(w2.z, hv.z, a2); a2 = fmaf(w2.w, hv.w, a2);
        }
#pragma unroll
        for (int off = 16; off > 0; off >>= 1) {
            a0 += __shfl_down_sync(0xffffffffu, a0, off);
            a1 += __shfl_down_sync(0xffffffffu, a1, off);
            a2 += __shfl_down_sync(0xffffffffu, a2, off);
        }
        if (lane == 0) {
            float r = sigmoidf_acc(gi0 + a0 + b0);
            float z = sigmoidf_acc(gi1 + a1 + b1);
            float n = tanhf(gi2 + r * (a2 + b2));
            float hv = (1.0f - z) * n + z * hprev;
            g_h[(t + 1) & 1][j] = hv;
            g_enc_out[(size_t)t * Hn + j] = hv;
        }
        grid_barrier();
    }
}

// ---------------- persistent decoder: 64 steps, all phases fused ----------------
__global__ void __launch_bounds__(NTHR, 2) dec_persistent(
    const float* __restrict__ dec_Wih, const float* __restrict__ dec_Whh,
    const float* __restrict__ dec_bih, const float* __restrict__ dec_bhh,
    const float* __restrict__ h2o_W, const float* __restrict__ h2o_b,
    const float* __restrict__ W_W, const float* __restrict__ W_b,
    const float* __restrict__ attn_W, const float* __restrict__ attn_b,
    const float* __restrict__ o2h_W, const float* __restrict__ o2h_b,
    float* __restrict__ d_out)
{
    const int warp = threadIdx.x >> 5;
    const int lane = threadIdx.x & 31;
    const int tid = threadIdx.x;
    const int j = blockIdx.x * WPB + warp;   // 0..2047
    const int gid = blockIdx.x * NTHR + tid;

    if (gid == 0) g_idx = -1;
    grid_barrier();

    for (int s = 0; s < DSTEP; s++) {
        const float* hin = g_h[s & 1];
        const float4* h4 = (const float4*)hin;

        // ---- A: Wd = h @ W_W^T + W_b (warp per j) ----
        {
            const float4* row = (const float4*)(W_W + (size_t)j * Hn);
            float acc = 0.f;
#pragma unroll 4
            for (int c = 0; c < Hn / 128; c++) {
                float4 w = __ldg(row + c * 32 + lane);
                float4 hv = __ldcg(h4 + c * 32 + lane);
                acc = fmaf(w.x, hv.x, acc); acc = fmaf(w.y, hv.y, acc);
                acc = fmaf(w.z, hv.z, acc); acc = fmaf(w.w, hv.w, acc);
            }
#pragma unroll
            for (int off = 16; off > 0; off >>= 1)
                acc += __shfl_down_sync(0xffffffffu, acc, off);
            if (lane == 0) g_Wd[j] = acc + __ldg(W_b + j);
        }
        grid_barrier();

        // ---- B: scores[t] = tanh(U[t]+Wd) . attn_W + attn_b (warps on blocks 0..63) ----
        if (blockIdx.x < 64) {
            const int t = blockIdx.x * WPB + warp;   // 0..511
            const float4* u4 = (const float4*)(g_U + (size_t)t * Hn);
            const float4* wd4 = (const float4*)g_Wd;
            const float4* aw4 = (const float4*)attn_W;
            float acc = 0.f;
#pragma unroll 4
            for (int c = 0; c < Hn / 128; c++) {
                float4 u = __ldg(u4 + c * 32 + lane);
                float4 d = __ldcg(wd4 + c * 32 + lane);
                float4 w = __ldg(aw4 + c * 32 + lane);
                acc = fmaf(tanhf(u.x + d.x), w.x, acc);
                acc = fmaf(tanhf(u.y + d.y), w.y, acc);
                acc = fmaf(tanhf(u.z + d.z), w.z, acc);
                acc = fmaf(tanhf(u.w + d.w), w.w, acc);
            }
#pragma unroll
            for (int off = 16; off > 0; off >>= 1)
                acc += __shfl_down_sync(0xffffffffu, acc, off);
            if (lane == 0) g_scores[t] = acc + __ldg(attn_b);
        }
        grid_barrier();

        // ---- C: softmax over 512 scores (block 0) ----
        if (blockIdx.x == 0) {
            __shared__ float s_red[8];
            float v0 = __ldcg(g_scores + tid);
            float v1 = __ldcg(g_scores + tid + 256);
            float m = fmaxf(v0, v1);
#pragma unroll
            for (int off = 16; off > 0; off >>= 1)
                m = fmaxf(m, __shfl_xor_sync(0xffffffffu, m, off));
            if (lane == 0) s_red[warp] = m;
            __syncthreads();
            float mx = s_red[0];
#pragma unroll
            for (int w = 1; w < 8; w++) mx = fmaxf(mx, s_red[w]);
            __syncthreads();
            float e0 = expf(v0 - mx), e1 = expf(v1 - mx);
            float sum = e0 + e1;
#pragma unroll
            for (int off = 16; off > 0; off >>= 1)
                sum += __shfl_xor_sync(0xffffffffu, sum, off);
            if (lane == 0) s_red[warp] = sum;
            __syncthreads();
            float tot = 0.f;
#pragma unroll
            for (int w = 0; w < 8; w++) tot += s_red[w];
            float inv = 1.0f / tot;
            float a0 = e0 * inv, a1 = e1 * inv;
            g_aw[tid] = a0;
            g_aw[tid + 256] = a1;
            d_out[DSTEP * OUTn + (size_t)s * Tn + tid] = a0;
            d_out[DSTEP * OUTn + (size_t)s * Tn + tid + 256] = a1;
        }
        grid_barrier();

        // ---- D1: ctx partials; block b: t-chunk b>>3 (16 t's), j-slice (b&7)*256 ----
        {
            const int chunk = blockIdx.x >> 3;        // 0..31
            const int jj = (blockIdx.x & 7) * 256 + tid;
            const int t0 = chunk * 16;
            float acc = 0.f;
#pragma unroll
            for (int t = 0; t < 16; t++) {
                float a = __ldcg(g_aw + t0 + t);
                acc = fmaf(a, __ldg(g_enc_out + (size_t)(t0 + t) * Hn + jj), acc);
            }
            g_ctx_part[chunk * Hn + jj] = acc;
        }
        grid_barrier();

        // ---- D2: reduce ctx partials, build din (blocks 0..7) ----
        if (blockIdx.x < 8) {
            const int jj = blockIdx.x * 256 + tid;
            float acc = 0.f;
#pragma unroll
            for (int p = 0; p < 32; p++)
                acc += __ldcg(g_ctx_part + p * Hn + jj);
            g_din[Hn + jj] = acc;
            int idx = __ldcg(&g_idx);
            float e = __ldg(o2h_b + jj);
            if (idx >= 0) e += __ldg(o2h_W + (size_t)jj * OUTn + idx);
            g_din[jj] = e;
        }
        grid_barrier();

        // ---- E: decoder GRU (warp per j) ----
        {
            const float4* d4 = (const float4*)g_din;
            const float4* ir = (const float4*)(dec_Wih + (size_t)j * DINn);
            const float4* iz = (const float4*)(dec_Wih + (size_t)(Hn + j) * DINn);
            const float4* in_ = (const float4*)(dec_Wih + (size_t)(2 * Hn + j) * DINn);
            const float4* hr = (const float4*)(dec_Whh + (size_t)j * Hn);
            const float4* hz = (const float4*)(dec_Whh + (size_t)(Hn + j) * Hn);
            const float4* hn = (const float4*)(dec_Whh + (size_t)(2 * Hn + j) * Hn);

            float a_r = 0.f, a_z = 0.f, a_in = 0.f, a_hn = 0.f;
#pragma unroll 4
            for (int c = 0; c < DINn / 128; c++) {
                float4 dv = __ldcg(d4 + c * 32 + lane);
                float4 w0 = __ldg(ir + c * 32 + lane);
                float4 w1 = __ldg(iz + c * 32 + lane);
                float4 w2 = __ldg(in_ + c * 32 + lane);
                a_r  = fmaf(w0.x, dv.x, a_r);  a_r  = fmaf(w0.y, dv.y, a_r);
                a_r  = fmaf(w0.z, dv.z, a_r);  a_r  = fmaf(w0.w, dv.w, a_r);
                a_z  = fmaf(w1.x, dv.x, a_z);  a_z  = fmaf(w1.y, dv.y, a_z);
                a_z  = fmaf(w1.z, dv.z, a_z);  a_z  = fmaf(w1.w, dv.w, a_z);
                a_in = fmaf(w2.x, dv.x, a_in); a_in = fmaf(w2.y, dv.y, a_in);
                a_in = fmaf(w2.z, dv.z, a_in); a_in = fmaf(w2.w, dv.w, a_in);
            }
            float hprev = 0.f;
            if (lane == 0) hprev = __ldcg(hin + j);
#pragma unroll 4
            for (int c = 0; c < Hn / 128; c++) {
                float4 hv = __ldcg(h4 + c * 32 + lane);
                float4 w0 = __ldg(hr + c * 32 + lane);
                float4 w1 = __ldg(hz + c * 32 + lane);
                float4 w2 = __ldg(hn + c * 32 + lane);
                a_r  = fmaf(w0.x, hv.x, a_r);  a_r  = fmaf(w0.y, hv.y, a_r);
                a_r  = fmaf(w0.z, hv.z, a_r);  a_r  = fmaf(w0.w, hv.w, a_r);
                a_z  = fmaf(w1.x, hv.x, a_z);  a_z  = fmaf(w1.y, hv.y, a_z);
                a_z  = fmaf(w1.z, hv.z, a_z);  a_z  = fmaf(w1.w, hv.w, a_z);
                a_hn = fmaf(w2.x, hv.x, a_hn); a_hn = fmaf(w2.y, hv.y, a_hn);
                a_hn = fmaf(w2.z, hv.z, a_hn); a_hn = fmaf(w2.w, hv.w, a_hn);
            }
#pragma unroll
            for (int off = 16; off > 0; off >>= 1) {
                a_r  += __shfl_down_sync(0xffffffffu, a_r,  off);
                a_z  += __shfl_down_sync(0xffffffffu, a_z,  off);
                a_in += __shfl_down_sync(0xffffffffu, a_in, off);
                a_hn += __shfl_down_sync(0xffffffffu, a_hn, off);
            }
            if (lane == 0) {
                float r = sigmoidf_acc(a_r + __ldg(dec_bih + j) + __ldg(dec_bhh + j));
                float z = sigmoidf_acc(a_z + __ldg(dec_bih + Hn + j) + __ldg(dec_bhh + Hn + j));
                float n = tanhf(a_in + __ldg(dec_bih + 2 * Hn + j)
                                + r * (a_hn + __ldg(dec_bhh + 2 * Hn + j)));
                g_h[(s + 1) & 1][j] = (1.0f - z) * n + z * hprev;
            }
        }
        grid_barrier();

        // ---- F1: logits (blocks 0..15, warp per output o) ----
        if (blockIdx.x < 16) {
            const int o = blockIdx.x * WPB + warp;   // 0..127
            const float4* hn4 = (const float4*)g_h[(s + 1) & 1];
            const float4* row = (const float4*)(h2o_W + (size_t)o * Hn);
            float acc = 0.f;
#pragma unroll 4
            for (int c = 0; c < Hn / 128; c++) {
                float4 w = __ldg(row + c * 32 + lane);
                float4 hv = __ldcg(hn4 + c * 32 + lane);
                acc = fmaf(w.x, hv.x, acc); acc = fmaf(w.y, hv.y, acc);
                acc = fmaf(w.z, hv.z, acc); acc = fmaf(w.w, hv.w, acc);
            }
#pragma unroll
            for (int off = 16; off > 0; off >>= 1)
                acc += __shfl_down_sync(0xffffffffu, acc, off);
            if (lane == 0) g_logits[o] = acc + __ldg(h2o_b + o);
        }
        grid_barrier();

        // ---- F2: log_softmax + argmax feedback (block 0, all 256 threads) ----
        if (blockIdx.x == 0) {
            __shared__ float s_val[8];
            __shared__ int   s_idx[8];
            __shared__ float s_mx, s_lse;
            __shared__ int   s_am;
            float v = -INFINITY;
            int vi = tid;
            if (tid < OUTn) v = __ldcg(g_logits + tid);
#pragma unroll
            for (int off = 16; off > 0; off >>= 1) {
                float ov = __shfl_xor_sync(0xffffffffu, v, off);
                int oi = __shfl_xor_sync(0xffffffffu, vi, off);
                if (ov > v || (ov == v && oi < vi)) { v = ov; vi = oi; }
            }
            if (lane == 0) { s_val[warp] = v; s_idx[warp] = vi; }
            __syncthreads();
            if (tid == 0) {
                float mv = s_val[0]; int mi = s_idx[0];
#pragma unroll
                for (int w = 1; w < 8; w++) {
                    if (s_val[w] > mv || (s_val[w] == mv && s_idx[w] < mi)) {
                        mv = s_val[w]; mi = s_idx[w];
                    }
                }
                s_mx = mv; s_am = mi;
            }
            __syncthreads();
            float mx = s_mx;
            float lv = (tid < OUTn) ? __ldcg(g_logits + tid) : 0.f;
            float e = (tid < OUTn) ? expf(lv - mx) : 0.f;
            float sum = e;
#pragma unroll
            for (int off = 16; off > 0; off >>= 1)
                sum += __shfl_xor_sync(0xffffffffu, sum, off);
            if (lane == 0) s_val[warp] = sum;
            __syncthreads();
            if (tid == 0) {
                float tot = 0.f;
#pragma unroll
                for (int w = 0; w < 8; w++) tot += s_val[w];
                s_lse = logf(tot);
                g_idx = s_am;
            }
            __syncthreads();
            if (tid < OUTn)
                d_out[(size_t)s * OUTn + tid] = lv - mx - s_lse;
        }
        grid_barrier();
    }
}

// ---------------- launch: 4 graph nodes total ----------------
extern "C" void kernel_launch(void* const* d_in, const int* in_sizes, int n_in,
                              void* d_out, int out_size)
{
    const float* x        = (const float*)d_in[0];
    const float* enc_Wih  = (const float*)d_in[1];
    const float* enc_Whh  = (const float*)d_in[2];
    const float* enc_bih  = (const float*)d_in[3];
    const float* enc_bhh  = (const float*)d_in[4];
    const float* dec_Wih  = (const float*)d_in[5];
    const float* dec_Whh  = (const float*)d_in[6];
    const float* dec_bih  = (const float*)d_in[7];
    const float* dec_bhh  = (const float*)d_in[8];
    const float* h2o_W    = (const float*)d_in[9];
    const float* h2o_b    = (const float*)d_in[10];
    const float* U_W      = (const float*)d_in[11];
    const float* U_b      = (const float*)d_in[12];
    const float* W_W      = (const float*)d_in[13];
    const float* W_b      = (const float*)d_in[14];
    const float* attn_W   = (const float*)d_in[15];
    const float* attn_b   = (const float*)d_in[16];
    const float* o2h_W    = (const float*)d_in[17];
    const float* o2h_b    = (const float*)d_in[18];
    float* out = (float*)d_out;
    (void)in_sizes; (void)n_in; (void)out_size;

    float *gi_ptr, *enc_out_ptr, *U_ptr;
    cudaGetSymbolAddress((void**)&gi_ptr, g_enc_gi);
    cudaGetSymbolAddress((void**)&enc_out_ptr, g_enc_out);
    cudaGetSymbolAddress((void**)&U_ptr, g_U);

    // gi = x @ enc_Wih^T + bih   (512 x 6144, K=128)
    gemm_nt_bias<<<dim3(G3n / 64, Tn / 64), 256>>>(x, enc_Wih, enc_bih, gi_ptr,
                                                   Tn, G3n, INn);
    // encoder: 512 sequential GRU steps in one persistent kernel
    enc_persistent<<<NBLK, NTHR>>>(enc_Whh, enc_bhh);

    // U = enc_out @ U_W^T + U_b  (512 x 2048, K=2048)
    gemm_nt_bias<<<dim3(Hn / 64, Tn / 64), 256>>>(enc_out_ptr, U_W, U_b, U_ptr,
                                                  Tn, Hn, Hn);
    // decoder: 64 sequential attention+GRU steps in one persistent kernel
    dec_persistent<<<NBLK, NTHR>>>(dec_Wih, dec_Whh, dec_bih, dec_bhh,
                                   h2o_W, h2o_b, W_W, W_b, attn_W, attn_b,
                                   o2h_W, o2h_b, out);
}

// round 3
// speedup vs baseline: 1.2573x; 1.2573x over previous
#include <cuda_runtime.h>
#include <math.h>

#define Hn    2048
#define Tn    512
#define INn   128
#define OUTn  128
#define G3n   6144
#define DSTEP 64
#define DINn  4096

#define NBLK  256
#define NTHR  256
#define WPB   (NTHR / 32)   // 8 warps per block

// ---------------- device scratch (no allocations allowed) ----------------
__device__ float g_enc_gi[Tn * G3n];    // x @ enc_Wih^T + bih
__device__ float g_enc_out[Tn * Hn];    // encoder hidden states
__device__ float g_U[Tn * Hn];          // enc_out @ U_W^T + U_b
__device__ float g_h[2][Hn];            // double-buffered hidden state
__device__ float g_Wd[Hn];
__device__ float g_scores[Tn];
__device__ float g_ctx_part[16 * Hn];   // ctx partial sums (16 t-chunks)
__device__ float g_din[DINn];
__device__ float g_logits[OUTn];
__device__ int   g_idx;                 // prev argmax (-1 => zero input)

// flag-based grid barrier state (separate per persistent kernel)
__device__ volatile unsigned g_arr_enc[NBLK];
__device__ volatile unsigned g_rel_enc;
__device__ volatile unsigned g_arr_dec[NBLK];
__device__ volatile unsigned g_rel_dec;

// Flag barrier: per-block arrival slots (no same-address atomic serialization).
// Block 0's threads each poll one slot in parallel; single release word.
__device__ __forceinline__ void gbar(volatile unsigned* arr, volatile unsigned* rel,
                                     unsigned gen) {
    __syncthreads();
    if (blockIdx.x == 0) {
        if (threadIdx.x > 0 && threadIdx.x < NBLK) {
            while (arr[threadIdx.x] < gen) { }
        }
        __threadfence();
        __syncthreads();
        if (threadIdx.x == 0) { *rel = gen; }
    } else {
        if (threadIdx.x == 0) {
            __threadfence();
            arr[blockIdx.x] = gen;
            while (*rel < gen) { }
            __threadfence();
        }
    }
    __syncthreads();
}

__device__ __forceinline__ float sigmoidf_acc(float x) {
    return 1.0f / (1.0f + expf(-x));
}

// ---------------- init: barrier state + h0 + feedback index ----------------
__global__ void init_kernel() {
    int i = blockIdx.x * blockDim.x + threadIdx.x;
    if (i < Hn) g_h[0][i] = 0.0f;
    if (i < NBLK) { g_arr_enc[i] = 0u; g_arr_dec[i] = 0u; }
    if (i == 0) { g_rel_enc = 0u; g_rel_dec = 0u; g_idx = -1; }
}

// ---------------- generic tiled GEMM:  C[M,N] = A[M,K] @ B[N,K]^T + bias[N] ----------------
__global__ void __launch_bounds__(256) gemm_nt_bias(
    const float* __restrict__ A, const float* __restrict__ B,
    const float* __restrict__ bias, float* __restrict__ C,
    int M, int N, int K)
{
    __shared__ float As[16][68];
    __shared__ float Bs[16][68];
    const int m0 = blockIdx.y * 64;
    const int n0 = blockIdx.x * 64;
    const int tid = threadIdx.x;
    const int tx = tid & 15;
    const int ty = tid >> 4;
    float c[4][4] = {};

    for (int k0 = 0; k0 < K; k0 += 16) {
#pragma unroll
        for (int i = 0; i < 4; i++) {
            int idx = tid + i * 256;
            int kk = idx & 15;
            int mm = idx >> 4;
            As[kk][mm] = A[(size_t)(m0 + mm) * K + k0 + kk];
            Bs[kk][mm] = B[(size_t)(n0 + mm) * K + k0 + kk];
        }
        __syncthreads();
#pragma unroll
        for (int kk = 0; kk < 16; kk++) {
            float4 a4 = *(const float4*)&As[kk][ty * 4];
            float4 b4 = *(const float4*)&Bs[kk][tx * 4];
            float av[4] = {a4.x, a4.y, a4.z, a4.w};
            float bv[4] = {b4.x, b4.y, b4.z, b4.w};
#pragma unroll
            for (int i = 0; i < 4; i++)
#pragma unroll
                for (int j = 0; j < 4; j++)
                    c[i][j] = fmaf(av[i], bv[j], c[i][j]);
        }
        __syncthreads();
    }
#pragma unroll
    for (int i = 0; i < 4; i++) {
        int m = m0 + ty * 4 + i;
#pragma unroll
        for (int j = 0; j < 4; j++) {
            int n = n0 + tx * 4 + j;
            C[(size_t)m * N + n] = c[i][j] + bias[n];
        }
    }
}

// ---------------- persistent encoder: 512 GRU steps ----------------
__global__ void __launch_bounds__(NTHR, 2) enc_persistent(
    const float* __restrict__ Whh, const float* __restrict__ bhh)
{
    __shared__ float sh[Hn];                 // staged h (8KB)
    const int warp = threadIdx.x >> 5;
    const int lane = threadIdx.x & 31;
    const int tid = threadIdx.x;
    const int j = blockIdx.x * WPB + warp;   // 0..2047

    const float4* __restrict__ r0 = (const float4*)(Whh + (size_t)j * Hn);
    const float4* __restrict__ r1 = (const float4*)(Whh + (size_t)(Hn + j) * Hn);
    const float4* __restrict__ r2 = (const float4*)(Whh + (size_t)(2 * Hn + j) * Hn);
    const float b0 = bhh[j], b1 = bhh[Hn + j], b2 = bhh[2 * Hn + j];

    unsigned gen = 0;
    float4* sh4 = (float4*)sh;

    for (int t = 0; t < Tn; t++) {
        const float4* hg4 = (const float4*)g_h[t & 1];
#pragma unroll
        for (int i = tid; i < Hn / 4; i += NTHR) sh4[i] = __ldcg(hg4 + i);
        __syncthreads();

        float a0 = 0.f, a1 = 0.f, a2 = 0.f;
#pragma unroll 4
        for (int c = 0; c < Hn / 128; c++) {
            float4 hv = sh4[c * 32 + lane];
            float4 w0 = __ldg(r0 + c * 32 + lane);
            float4 w1 = __ldg(r1 + c * 32 + lane);
            float4 w2 = __ldg(r2 + c * 32 + lane);
            a0 = fmaf(w0.x, hv.x, a0); a0 = fmaf(w0.y, hv.y, a0);
            a0 = fmaf(w0.z, hv.z, a0); a0 = fmaf(w0.w, hv.w, a0);
            a1 = fmaf(w1.x, hv.x, a1); a1 = fmaf(w1.y, hv.y, a1);
            a1 = fmaf(w1.z, hv.z, a1); a1 = fmaf(w1.w, hv.w, a1);
            a2 = fmaf(w2.x, hv.x, a2); a2 = fmaf(w2.y, hv.y, a2);
            a2 = fmaf(w2.z, hv.z, a2); a2 = fmaf(w2.w, hv.w, a2);
        }
#pragma unroll
        for (int off = 16; off > 0; off >>= 1) {
            a0 += __shfl_down_sync(0xffffffffu, a0, off);
            a1 += __shfl_down_sync(0xffffffffu, a1, off);
            a2 += __shfl_down_sync(0xffffffffu, a2, off);
        }
        if (lane == 0) {
            const float* gi = g_enc_gi + (size_t)t * G3n;
            float r = sigmoidf_acc(__ldcs(gi + j) + a0 + b0);
            float z = sigmoidf_acc(__ldcs(gi + Hn + j) + a1 + b1);
            float n = tanhf(__ldcs(gi + 2 * Hn + j) + r * (a2 + b2));
            float hv = (1.0f - z) * n + z * sh[j];
            g_h[(t + 1) & 1][j] = hv;
            g_enc_out[(size_t)t * Hn + j] = hv;
        }
        gen++;
        gbar(g_arr_enc, &g_rel_enc, gen);
    }
}

// ---------------- persistent decoder: 64 steps, 5 barriers/step ----------------
__global__ void __launch_bounds__(NTHR, 2) dec_persistent(
    const float* __restrict__ dec_Wih, const float* __restrict__ dec_Whh,
    const float* __restrict__ dec_bih, const float* __restrict__ dec_bhh,
    const float* __restrict__ h2o_W, const float* __restrict__ h2o_b,
    const float* __restrict__ W_W, const float* __restrict__ W_b,
    const float* __restrict__ attn_W, const float* __restrict__ attn_b,
    const float* __restrict__ o2h_W, const float* __restrict__ o2h_b,
    float* __restrict__ d_out)
{
    __shared__ float sbuf[DINn + Hn];   // 24KB staging
    __shared__ float s_red[WPB];
    __shared__ float s_fval[WPB];
    __shared__ int   s_fidx[WPB];
    __shared__ float s_mx, s_lse;
    __shared__ int   s_am;

    const int warp = threadIdx.x >> 5;
    const int lane = threadIdx.x & 31;
    const int tid = threadIdx.x;
    const int bid = blockIdx.x;
    const int j = bid * WPB + warp;     // 0..2047
    unsigned gen = 0;

    for (int s = 0; s < DSTEP; s++) {
        const float* hin = g_h[s & 1];

        // ---- Phase A: Wd = h @ W_W^T + W_b (all blocks, warp per j) ----
        {
            float4* sh4 = (float4*)sbuf;
            const float4* hg4 = (const float4*)hin;
#pragma unroll
            for (int i = tid; i < Hn / 4; i += NTHR) sh4[i] = __ldcg(hg4 + i);
            __syncthreads();
            const float4* row = (const float4*)(W_W + (size_t)j * Hn);
            float acc = 0.f;
#pragma unroll 4
            for (int c = 0; c < Hn / 128; c++) {
                float4 w = __ldg(row + c * 32 + lane);
                float4 hv = sh4[c * 32 + lane];
                acc = fmaf(w.x, hv.x, acc); acc = fmaf(w.y, hv.y, acc);
                acc = fmaf(w.z, hv.z, acc); acc = fmaf(w.w, hv.w, acc);
            }
#pragma unroll
            for (int off = 16; off > 0; off >>= 1)
                acc += __shfl_down_sync(0xffffffffu, acc, off);
            if (lane == 0) g_Wd[j] = acc + __ldg(W_b + j);
        }
        gen++; gbar(g_arr_dec, &g_rel_dec, gen);

        // ---- Phase B: scores (blocks 0..63) | logits of h_s (blocks 64..79, s>0) ----
        if (bid < 64) {
            float4* swd = (float4*)sbuf;
            const float4* wd4 = (const float4*)g_Wd;
#pragma unroll
            for (int i = tid; i < Hn / 4; i += NTHR) swd[i] = __ldcg(wd4 + i);
            __syncthreads();
            const int t = bid * WPB + warp;   // 0..511
            const float4* u4 = (const float4*)(g_U + (size_t)t * Hn);
            const float4* aw4 = (const float4*)attn_W;
            float acc = 0.f;
#pragma unroll 4
            for (int c = 0; c < Hn / 128; c++) {
                float4 u = __ldg(u4 + c * 32 + lane);
                float4 d = swd[c * 32 + lane];
                float4 w = __ldg(aw4 + c * 32 + lane);
                acc = fmaf(tanhf(u.x + d.x), w.x, acc);
                acc = fmaf(tanhf(u.y + d.y), w.y, acc);
                acc = fmaf(tanhf(u.z + d.z), w.z, acc);
                acc = fmaf(tanhf(u.w + d.w), w.w, acc);
            }
#pragma unroll
            for (int off = 16; off > 0; off >>= 1)
                acc += __shfl_down_sync(0xffffffffu, acc, off);
            if (lane == 0) g_scores[t] = acc + __ldg(attn_b);
        } else if (bid < 80 && s > 0) {
            const int o = (bid - 64) * WPB + warp;   // 0..127
            const float4* hg4 = (const float4*)hin;
            const float4* row = (const float4*)(h2o_W + (size_t)o * Hn);
            float acc = 0.f;
#pragma unroll 4
            for (int c = 0; c < Hn / 128; c++) {
                float4 w = __ldg(row + c * 32 + lane);
                float4 hv = __ldcg(hg4 + c * 32 + lane);
                acc = fmaf(w.x, hv.x, acc); acc = fmaf(w.y, hv.y, acc);
                acc = fmaf(w.z, hv.z, acc); acc = fmaf(w.w, hv.w, acc);
            }
#pragma unroll
            for (int off = 16; off > 0; off >>= 1)
                acc += __shfl_down_sync(0xffffffffu, acc, off);
            if (lane == 0) g_logits[o] = acc + __ldg(h2o_b + o);
        }
        gen++; gbar(g_arr_dec, &g_rel_dec, gen);

        // ---- Phase C: local softmax + ctx partials (0..127) | attns writeout (129)
        //               | prev-step log_softmax + argmax (128, s>0) ----
        if (bid < 128 || bid == 129) {
            // redundant local softmax over the 512 scores (2KB read, cheap)
            float v0 = __ldcg(g_scores + tid);
            float v1 = __ldcg(g_scores + tid + 256);
            float m = fmaxf(v0, v1);
#pragma unroll
            for (int off = 16; off > 0; off >>= 1)
                m = fmaxf(m, __shfl_xor_sync(0xffffffffu, m, off));
            if (lane == 0) s_red[warp] = m;
            __syncthreads();
            float mx = s_red[0];
#pragma unroll
            for (int w = 1; w < WPB; w++) mx = fmaxf(mx, s_red[w]);
            __syncthreads();
            float e0 = expf(v0 - mx), e1 = expf(v1 - mx);
            float sum = e0 + e1;
#pragma unroll
            for (int off = 16; off > 0; off >>= 1)
                sum += __shfl_xor_sync(0xffffffffu, sum, off);
            if (lane == 0) s_red[warp] = sum;
            __syncthreads();
            float tot = 0.f;
#pragma unroll
            for (int w = 0; w < WPB; w++) tot += s_red[w];
            float inv = 1.0f / tot;
            sbuf[tid] = e0 * inv;
            sbuf[tid + 256] = e1 * inv;
            __syncthreads();
            if (bid == 129) {
                d_out[DSTEP * OUTn + (size_t)s * Tn + tid] = sbuf[tid];
                d_out[DSTEP * OUTn + (size_t)s * Tn + tid + 256] = sbuf[tid + 256];
            } else {
                const int chunk = bid >> 3;              // 0..15
                const int jj = (bid & 7) * 256 + tid;
                const int t0 = chunk * 32;
                float acc = 0.f;
#pragma unroll
                for (int tt = 0; tt < 32; tt++)
                    acc = fmaf(sbuf[t0 + tt],
                               __ldg(g_enc_out + (size_t)(t0 + tt) * Hn + jj), acc);
                g_ctx_part[chunk * Hn + jj] = acc;
            }
        } else if (bid == 128 && s > 0) {
            // log_softmax + argmax of step s-1 logits
            float lv = (tid < OUTn) ? __ldcg(g_logits + tid) : -INFINITY;
            float v = lv;
            int vi = tid;
#pragma unroll
            for (int off = 16; off > 0; off >>= 1) {
                float ov = __shfl_xor_sync(0xffffffffu, v, off);
                int oi = __shfl_xor_sync(0xffffffffu, vi, off);
                if (ov > v || (ov == v && oi < vi)) { v = ov; vi = oi; }
            }
            if (lane == 0) { s_fval[warp] = v; s_fidx[warp] = vi; }
            __syncthreads();
            if (tid == 0) {
                float mv = s_fval[0]; int mi = s_fidx[0];
#pragma unroll
                for (int w = 1; w < WPB; w++)
                    if (s_fval[w] > mv || (s_fval[w] == mv && s_fidx[w] < mi)) {
                        mv = s_fval[w]; mi = s_fidx[w];
                    }
                s_mx = mv; s_am = mi;
            }
            __syncthreads();
            float mx = s_mx;
            float e = (tid < OUTn) ? expf(lv - mx) : 0.f;
            float sum = e;
#pragma unroll
            for (int off = 16; off > 0; off >>= 1)
                sum += __shfl_xor_sync(0xffffffffu, sum, off);
            if (lane == 0) s_fval[warp] = sum;
            __syncthreads();
            if (tid == 0) {
                float tot = 0.f;
#pragma unroll
                for (int w = 0; w < WPB; w++) tot += s_fval[w];
                s_lse = logf(tot);
                g_idx = s_am;
            }
            __syncthreads();
            if (tid < OUTn)
                d_out[(size_t)(s - 1) * OUTn + tid] = lv - mx - s_lse;
        }
        gen++; gbar(g_arr_dec, &g_rel_dec, gen);

        // ---- Phase D: reduce ctx partials + build din (blocks 0..7) ----
        if (bid < 8) {
            const int jj = bid * 256 + tid;
            float acc = 0.f;
#pragma unroll
            for (int p = 0; p < 16; p++)
                acc += __ldcg(g_ctx_part + p * Hn + jj);
            g_din[Hn + jj] = acc;
            int idx = __ldcg(&g_idx);
            float e = __ldg(o2h_b + jj);
            if (idx >= 0) e += __ldg(o2h_W + (size_t)jj * OUTn + idx);
            g_din[jj] = e;
        }
        gen++; gbar(g_arr_dec, &g_rel_dec, gen);

        // ---- Phase E: decoder GRU (all blocks, warp per j) ----
        {
            float* sdin = sbuf;
            float* shh = sbuf + DINn;
            float4* sdin4 = (float4*)sdin;
            float4* shh4 = (float4*)shh;
            const float4* dg4 = (const float4*)g_din;
            const float4* hg4 = (const float4*)hin;
#pragma unroll
            for (int i = tid; i < DINn / 4; i += NTHR) sdin4[i] = __ldcg(dg4 + i);
#pragma unroll
            for (int i = tid; i < Hn / 4; i += NTHR) shh4[i] = __ldcg(hg4 + i);
            __syncthreads();

            const float4* ir = (const float4*)(dec_Wih + (size_t)j * DINn);
            const float4* iz = (const float4*)(dec_Wih + (size_t)(Hn + j) * DINn);
            const float4* in_ = (const float4*)(dec_Wih + (size_t)(2 * Hn + j) * DINn);
            const float4* hr = (const float4*)(dec_Whh + (size_t)j * Hn);
            const float4* hz = (const float4*)(dec_Whh + (size_t)(Hn + j) * Hn);
            const float4* hn = (const float4*)(dec_Whh + (size_t)(2 * Hn + j) * Hn);

            float a_r = 0.f, a_z = 0.f, a_in = 0.f, a_hn = 0.f;
#pragma unroll 4
            for (int c = 0; c < DINn / 128; c++) {
                float4 dv = sdin4[c * 32 + lane];
                float4 w0 = __ldcs(ir + c * 32 + lane);   // streamed, evict-first
                float4 w1 = __ldcs(iz + c * 32 + lane);
                float4 w2 = __ldcs(in_ + c * 32 + lane);
                a_r  = fmaf(w0.x, dv.x, a_r);  a_r  = fmaf(w0.y, dv.y, a_r);
                a_r  = fmaf(w0.z, dv.z, a_r);  a_r  = fmaf(w0.w, dv.w, a_r);
                a_z  = fmaf(w1.x, dv.x, a_z);  a_z  = fmaf(w1.y, dv.y, a_z);
                a_z  = fmaf(w1.z, dv.z, a_z);  a_z  = fmaf(w1.w, dv.w, a_z);
                a_in = fmaf(w2.x, dv.x, a_in); a_in = fmaf(w2.y, dv.y, a_in);
                a_in = fmaf(w2.z, dv.z, a_in); a_in = fmaf(w2.w, dv.w, a_in);
            }
#pragma unroll 4
            for (int c = 0; c < Hn / 128; c++) {
                float4 hv = shh4[c * 32 + lane];
                float4 w0 = __ldg(hr + c * 32 + lane);
                float4 w1 = __ldg(hz + c * 32 + lane);
                float4 w2 = __ldg(hn + c * 32 + lane);
                a_r  = fmaf(w0.x, hv.x, a_r);  a_r  = fmaf(w0.y, hv.y, a_r);
                a_r  = fmaf(w0.z, hv.z, a_r);  a_r  = fmaf(w0.w, hv.w, a_r);
                a_z  = fmaf(w1.x, hv.x, a_z);  a_z  = fmaf(w1.y, hv.y, a_z);
                a_z  = fmaf(w1.z, hv.z, a_z);  a_z  = fmaf(w1.w, hv.w, a_z);
                a_hn = fmaf(w2.x, hv.x, a_hn); a_hn = fmaf(w2.y, hv.y, a_hn);
                a_hn = fmaf(w2.z, hv.z, a_hn); a_hn = fmaf(w2.w, hv.w, a_hn);
            }
#pragma unroll
            for (int off = 16; off > 0; off >>= 1) {
                a_r  += __shfl_down_sync(0xffffffffu, a_r,  off);
                a_z  += __shfl_down_sync(0xffffffffu, a_z,  off);
                a_in += __shfl_down_sync(0xffffffffu, a_in, off);
                a_hn += __shfl_down_sync(0xffffffffu, a_hn, off);
            }
            if (lane == 0) {
                float r = sigmoidf_acc(a_r + __ldg(dec_bih + j) + __ldg(dec_bhh + j));
                float z = sigmoidf_acc(a_z + __ldg(dec_bih + Hn + j) + __ldg(dec_bhh + Hn + j));
                float n = tanhf(a_in + __ldg(dec_bih + 2 * Hn + j)
                                + r * (a_hn + __ldg(dec_bhh + 2 * Hn + j)));
                g_h[(s + 1) & 1][j] = (1.0f - z) * n + z * shh[j];
            }
        }
        gen++; gbar(g_arr_dec, &g_rel_dec, gen);
    }

    // ---- tail: logits + log_softmax for output row DSTEP-1 (uses h_64) ----
    if (bid < 16) {
        const int o = bid * WPB + warp;
        const float4* hg4 = (const float4*)g_h[DSTEP & 1];
        const float4* row = (const float4*)(h2o_W + (size_t)o * Hn);
        float acc = 0.f;
#pragma unroll 4
        for (int c = 0; c < Hn / 128; c++) {
            float4 w = __ldg(row + c * 32 + lane);
            float4 hv = __ldcg(hg4 + c * 32 + lane);
            acc = fmaf(w.x, hv.x, acc); acc = fmaf(w.y, hv.y, acc);
            acc = fmaf(w.z, hv.z, acc); acc = fmaf(w.w, hv.w, acc);
        }
#pragma unroll
        for (int off = 16; off > 0; off >>= 1)
            acc += __shfl_down_sync(0xffffffffu, acc, off);
        if (lane == 0) g_logits[o] = acc + __ldg(h2o_b + o);
    }
    gen++; gbar(g_arr_dec, &g_rel_dec, gen);

    if (bid == 0) {
        float lv = (tid < OUTn) ? __ldcg(g_logits + tid) : -INFINITY;
        float v = lv;
#pragma unroll
        for (int off = 16; off > 0; off >>= 1)
            v = fmaxf(v, __shfl_xor_sync(0xffffffffu, v, off));
        if (lane == 0) s_fval[warp] = v;
        __syncthreads();
        if (tid == 0) {
            float mv = s_fval[0];
#pragma unroll
            for (int w = 1; w < WPB; w++) mv = fmaxf(mv, s_fval[w]);
            s_mx = mv;
        }
        __syncthreads();
        float mx = s_mx;
        float e = (tid < OUTn) ? expf(lv - mx) : 0.f;
        float sum = e;
#pragma unroll
        for (int off = 16; off > 0; off >>= 1)
            sum += __shfl_xor_sync(0xffffffffu, sum, off);
        if (lane == 0) s_fval[warp] = sum;
        __syncthreads();
        if (tid == 0) {
            float tot = 0.f;
#pragma unroll
            for (int w = 0; w < WPB; w++) tot += s_fval[w];
            s_lse = logf(tot);
        }
        __syncthreads();
        if (tid < OUTn)
            d_out[(size_t)(DSTEP - 1) * OUTn + tid] = lv - mx - s_lse;
    }
}

// ---------------- launch: 5 graph nodes ----------------
extern "C" void kernel_launch(void* const* d_in, const int* in_sizes, int n_in,
                              void* d_out, int out_size)
{
    const float* x        = (const float*)d_in[0];
    const float* enc_Wih  = (const float*)d_in[1];
    const float* enc_Whh  = (const float*)d_in[2];
    const float* enc_bih  = (const float*)d_in[3];
    const float* enc_bhh  = (const float*)d_in[4];
    const float* dec_Wih  = (const float*)d_in[5];
    const float* dec_Whh  = (const float*)d_in[6];
    const float* dec_bih  = (const float*)d_in[7];
    const float* dec_bhh  = (const float*)d_in[8];
    const float* h2o_W    = (const float*)d_in[9];
    const float* h2o_b    = (const float*)d_in[10];
    const float* U_W      = (const float*)d_in[11];
    const float* U_b      = (const float*)d_in[12];
    const float* W_W      = (const float*)d_in[13];
    const float* W_b      = (const float*)d_in[14];
    const float* attn_W   = (const float*)d_in[15];
    const float* attn_b   = (const float*)d_in[16];
    const float* o2h_W    = (const float*)d_in[17];
    const float* o2h_b    = (const float*)d_in[18];
    float* out = (float*)d_out;
    (void)in_sizes; (void)n_in; (void)out_size;

    float *gi_ptr, *enc_out_ptr, *U_ptr;
    cudaGetSymbolAddress((void**)&gi_ptr, g_enc_gi);
    cudaGetSymbolAddress((void**)&enc_out_ptr, g_enc_out);
    cudaGetSymbolAddress((void**)&U_ptr, g_U);

    init_kernel<<<8, 256>>>();

    // gi = x @ enc_Wih^T + bih   (512 x 6144, K=128)
    gemm_nt_bias<<<dim3(G3n / 64, Tn / 64), 256>>>(x, enc_Wih, enc_bih, gi_ptr,
                                                   Tn, G3n, INn);
    // encoder: 512 sequential GRU steps in one persistent kernel
    enc_persistent<<<NBLK, NTHR>>>(enc_Whh, enc_bhh);

    // U = enc_out @ U_W^T + U_b  (512 x 2048, K=2048)
    gemm_nt_bias<<<dim3(Hn / 64, Tn / 64), 256>>>(enc_out_ptr, U_W, U_b, U_ptr,
                                                  Tn, Hn, Hn);
    // decoder: 64 sequential attention+GRU steps in one persistent kernel
    dec_persistent<<<NBLK, NTHR>>>(dec_Wih, dec_Whh, dec_bih, dec_bhh,
                                   h2o_W, h2o_b, W_W, W_b, attn_W, attn_b,
                                   o2h_W, o2h_b, out);
}

// round 4
// speedup vs baseline: 1.4813x; 1.1782x over previous
#include <cuda_runtime.h>
#include <cuda_bf16.h>
#include <math.h>

#define Hn    2048
#define Tn    512
#define INn   128
#define OUTn  128
#define G3n   6144
#define DSTEP 64
#define DINn  4096

#define NBLK  256
#define NTHR  256
#define WPB   (NTHR / 32)   // 8 warps per block

// ---------------- device scratch (no allocations allowed) ----------------
__device__ float g_enc_gi[Tn * G3n];    // x @ enc_Wih^T + bih
__device__ float g_enc_out[Tn * Hn];    // encoder hidden states
__device__ float g_U[Tn * Hn];          // enc_out @ U_W^T + U_b
__device__ float g_h[2][Hn];            // double-buffered hidden state
__device__ float g_Wd[Hn];
__device__ float g_scores[Tn];
__device__ float g_ctx_part[16 * Hn];   // ctx partial sums
__device__ float g_din[DINn];
__device__ float g_logits[OUTn];
__device__ int   g_idx;                 // prev argmax (-1 => zero input)

// bf16 weight copies (converted on device each run)
__device__ __nv_bfloat16 g_decWih_bf[G3n * DINn];  // ~50 MB
__device__ __nv_bfloat16 g_decWhh_bf[G3n * Hn];    // ~25 MB
__device__ __nv_bfloat16 g_WW_bf[Hn * Hn];         // ~8 MB

// flag-based grid barrier state
__device__ volatile unsigned g_arr_enc[NBLK];
__device__ volatile unsigned g_rel_enc;
__device__ volatile unsigned g_arr_dec[NBLK];
__device__ volatile unsigned g_rel_dec;

__device__ __forceinline__ void gbar(volatile unsigned* arr, volatile unsigned* rel,
                                     unsigned gen) {
    __syncthreads();
    if (blockIdx.x == 0) {
        if (threadIdx.x > 0 && threadIdx.x < NBLK) {
            while (arr[threadIdx.x] < gen) { }
        }
        __threadfence();
        __syncthreads();
        if (threadIdx.x == 0) { *rel = gen; }
    } else {
        if (threadIdx.x == 0) {
            __threadfence();
            arr[blockIdx.x] = gen;
            while (*rel < gen) { }
            __threadfence();
        }
    }
    __syncthreads();
}

__device__ __forceinline__ float sigmoidf_acc(float x) {
    return 1.0f / (1.0f + expf(-x));
}
__device__ __forceinline__ float blo(unsigned u) { return __int_as_float(u << 16); }
__device__ __forceinline__ float bhi(unsigned u) { return __int_as_float(u & 0xffff0000u); }

// ---------------- init ----------------
__global__ void init_kernel() {
    int i = blockIdx.x * blockDim.x + threadIdx.x;
    if (i < Hn) g_h[0][i] = 0.0f;
    if (i < NBLK) { g_arr_enc[i] = 0u; g_arr_dec[i] = 0u; }
    if (i == 0) { g_rel_enc = 0u; g_rel_dec = 0u; g_idx = -1; }
}

// ---------------- fp32 -> bf16 conversion (pairs) ----------------
__global__ void f2bf_kernel(const float* __restrict__ in,
                            __nv_bfloat16* __restrict__ out, int n_pairs) {
    int stride = gridDim.x * blockDim.x;
    const float2* in2 = (const float2*)in;
    __nv_bfloat162* out2 = (__nv_bfloat162*)out;
    for (int i = blockIdx.x * blockDim.x + threadIdx.x; i < n_pairs; i += stride)
        out2[i] = __float22bfloat162_rn(in2[i]);
}

// ---------------- generic tiled GEMM:  C[M,N] = A[M,K] @ B[N,K]^T + bias[N] ----------------
__global__ void __launch_bounds__(256) gemm_nt_bias(
    const float* __restrict__ A, const float* __restrict__ B,
    const float* __restrict__ bias, float* __restrict__ C,
    int M, int N, int K)
{
    __shared__ float As[16][68];
    __shared__ float Bs[16][68];
    const int m0 = blockIdx.y * 64;
    const int n0 = blockIdx.x * 64;
    const int tid = threadIdx.x;
    const int tx = tid & 15;
    const int ty = tid >> 4;
    float c[4][4] = {};

    for (int k0 = 0; k0 < K; k0 += 16) {
#pragma unroll
        for (int i = 0; i < 4; i++) {
            int idx = tid + i * 256;
            int kk = idx & 15;
            int mm = idx >> 4;
            As[kk][mm] = A[(size_t)(m0 + mm) * K + k0 + kk];
            Bs[kk][mm] = B[(size_t)(n0 + mm) * K + k0 + kk];
        }
        __syncthreads();
#pragma unroll
        for (int kk = 0; kk < 16; kk++) {
            float4 a4 = *(const float4*)&As[kk][ty * 4];
            float4 b4 = *(const float4*)&Bs[kk][tx * 4];
            float av[4] = {a4.x, a4.y, a4.z, a4.w};
            float bv[4] = {b4.x, b4.y, b4.z, b4.w};
#pragma unroll
            for (int i = 0; i < 4; i++)
#pragma unroll
                for (int j = 0; j < 4; j++)
                    c[i][j] = fmaf(av[i], bv[j], c[i][j]);
        }
        __syncthreads();
    }
#pragma unroll
    for (int i = 0; i < 4; i++) {
        int m = m0 + ty * 4 + i;
#pragma unroll
        for (int j = 0; j < 4; j++) {
            int n = n0 + tx * 4 + j;
            C[(size_t)m * N + n] = c[i][j] + bias[n];
        }
    }
}

// ---------------- persistent encoder: bf16 weights resident in SMEM ----------------
// Dynamic smem: [0, 96KB) warp-owned Whh rows as bf16 (uint32-packed),
//               [96KB, 104KB) fp32 h staging.
__global__ void __launch_bounds__(NTHR, 2) enc_persistent(
    const float* __restrict__ Whh, const float* __restrict__ bhh)
{
    extern __shared__ char smem_raw[];
    unsigned* sw = (unsigned*)smem_raw;                      // WPB*3*1024 u32
    float* shh = (float*)(smem_raw + WPB * 3 * 1024 * 4);    // Hn floats
    float4* shh4 = (float4*)shh;

    const int warp = threadIdx.x >> 5;
    const int lane = threadIdx.x & 31;
    const int tid = threadIdx.x;
    const int j = blockIdx.x * WPB + warp;   // 0..2047

    // load + convert this warp's 3 rows into smem (once)
#pragma unroll
    for (int r = 0; r < 3; r++) {
        const float2* src = (const float2*)(Whh + (size_t)(r * Hn + j) * Hn);
        unsigned* dst = sw + (warp * 3 + r) * 1024;
        for (int i = lane; i < 1024; i += 32) {
            __nv_bfloat162 b2 = __float22bfloat162_rn(__ldg(src + i));
            dst[i] = *(unsigned*)&b2;
        }
    }
    const uint4* w0p = (const uint4*)(sw + (warp * 3 + 0) * 1024);
    const uint4* w1p = (const uint4*)(sw + (warp * 3 + 1) * 1024);
    const uint4* w2p = (const uint4*)(sw + (warp * 3 + 2) * 1024);
    const float b0 = bhh[j], b1 = bhh[Hn + j], b2v = bhh[2 * Hn + j];

    unsigned gen = 0;
    __syncthreads();

    for (int t = 0; t < Tn; t++) {
        const float4* hg4 = (const float4*)g_h[t & 1];
#pragma unroll
        for (int i = tid; i < Hn / 4; i += NTHR) shh4[i] = __ldcg(hg4 + i);
        __syncthreads();

        float a0 = 0.f, a1 = 0.f, a2 = 0.f;
#pragma unroll
        for (int c = 0; c < 8; c++) {
            const int idx = c * 32 + lane;
            float4 hA = shh4[2 * idx];
            float4 hB = shh4[2 * idx + 1];
            uint4 u0 = w0p[idx];
            uint4 u1 = w1p[idx];
            uint4 u2 = w2p[idx];
            a0 = fmaf(blo(u0.x), hA.x, a0); a0 = fmaf(bhi(u0.x), hA.y, a0);
            a0 = fmaf(blo(u0.y), hA.z, a0); a0 = fmaf(bhi(u0.y), hA.w, a0);
            a0 = fmaf(blo(u0.z), hB.x, a0); a0 = fmaf(bhi(u0.z), hB.y, a0);
            a0 = fmaf(blo(u0.w), hB.z, a0); a0 = fmaf(bhi(u0.w), hB.w, a0);
            a1 = fmaf(blo(u1.x), hA.x, a1); a1 = fmaf(bhi(u1.x), hA.y, a1);
            a1 = fmaf(blo(u1.y), hA.z, a1); a1 = fmaf(bhi(u1.y), hA.w, a1);
            a1 = fmaf(blo(u1.z), hB.x, a1); a1 = fmaf(bhi(u1.z), hB.y, a1);
            a1 = fmaf(blo(u1.w), hB.z, a1); a1 = fmaf(bhi(u1.w), hB.w, a1);
            a2 = fmaf(blo(u2.x), hA.x, a2); a2 = fmaf(bhi(u2.x), hA.y, a2);
            a2 = fmaf(blo(u2.y), hA.z, a2); a2 = fmaf(bhi(u2.y), hA.w, a2);
            a2 = fmaf(blo(u2.z), hB.x, a2); a2 = fmaf(bhi(u2.z), hB.y, a2);
            a2 = fmaf(blo(u2.w), hB.z, a2); a2 = fmaf(bhi(u2.w), hB.w, a2);
        }
#pragma unroll
        for (int off = 16; off > 0; off >>= 1) {
            a0 += __shfl_down_sync(0xffffffffu, a0, off);
            a1 += __shfl_down_sync(0xffffffffu, a1, off);
            a2 += __shfl_down_sync(0xffffffffu, a2, off);
        }
        if (lane == 0) {
            const float* gi = g_enc_gi + (size_t)t * G3n;
            float r = sigmoidf_acc(__ldcs(gi + j) + a0 + b0);
            float z = sigmoidf_acc(__ldcs(gi + Hn + j) + a1 + b1);
            float n = tanhf(__ldcs(gi + 2 * Hn + j) + r * (a2 + b2v));
            float hv = (1.0f - z) * n + z * shh[j];
            g_h[(t + 1) & 1][j] = hv;
            g_enc_out[(size_t)t * Hn + j] = hv;
        }
        gen++;
        gbar(g_arr_enc, &g_rel_enc, gen);
    }
}

// ---------------- persistent decoder: bf16 weights (L2-resident) ----------------
__global__ void __launch_bounds__(NTHR, 2) dec_persistent(
    const float* __restrict__ dec_bih, const float* __restrict__ dec_bhh,
    const float* __restrict__ h2o_W, const float* __restrict__ h2o_b,
    const float* __restrict__ W_b,
    const float* __restrict__ attn_W, const float* __restrict__ attn_b,
    const float* __restrict__ o2h_W, const float* __restrict__ o2h_b,
    float* __restrict__ d_out)
{
    __shared__ float sbuf[DINn + Hn];   // 24KB staging
    __shared__ float s_red[WPB];
    __shared__ float s_fval[WPB];
    __shared__ int   s_fidx[WPB];
    __shared__ float s_mx, s_lse;
    __shared__ int   s_am;

    const int warp = threadIdx.x >> 5;
    const int lane = threadIdx.x & 31;
    const int tid = threadIdx.x;
    const int bid = blockIdx.x;
    const int j = bid * WPB + warp;     // 0..2047
    unsigned gen = 0;

    for (int s = 0; s < DSTEP; s++) {
        const float* hin = g_h[s & 1];

        // ---- Phase A: Wd = h @ W_W^T + W_b (bf16 weights) ----
        {
            float4* sh4 = (float4*)sbuf;
            const float4* hg4 = (const float4*)hin;
#pragma unroll
            for (int i = tid; i < Hn / 4; i += NTHR) sh4[i] = __ldcg(hg4 + i);
            __syncthreads();
            const uint4* row = (const uint4*)g_WW_bf + (size_t)j * (Hn / 8);
            float acc = 0.f;
#pragma unroll
            for (int c = 0; c < 8; c++) {
                const int idx = c * 32 + lane;
                float4 hA = sh4[2 * idx];
                float4 hB = sh4[2 * idx + 1];
                uint4 u = __ldg(row + idx);
                acc = fmaf(blo(u.x), hA.x, acc); acc = fmaf(bhi(u.x), hA.y, acc);
                acc = fmaf(blo(u.y), hA.z, acc); acc = fmaf(bhi(u.y), hA.w, acc);
                acc = fmaf(blo(u.z), hB.x, acc); acc = fmaf(bhi(u.z), hB.y, acc);
                acc = fmaf(blo(u.w), hB.z, acc); acc = fmaf(bhi(u.w), hB.w, acc);
            }
#pragma unroll
            for (int off = 16; off > 0; off >>= 1)
                acc += __shfl_down_sync(0xffffffffu, acc, off);
            if (lane == 0) g_Wd[j] = acc + __ldg(W_b + j);
        }
        gen++; gbar(g_arr_dec, &g_rel_dec, gen);

        // ---- Phase B: scores (blocks 0..63, fp32) | logits of h_s (64..79, s>0) ----
        if (bid < 64) {
            float4* swd = (float4*)sbuf;
            const float4* wd4 = (const float4*)g_Wd;
#pragma unroll
            for (int i = tid; i < Hn / 4; i += NTHR) swd[i] = __ldcg(wd4 + i);
            __syncthreads();
            const int t = bid * WPB + warp;   // 0..511
            const float4* u4 = (const float4*)(g_U + (size_t)t * Hn);
            const float4* aw4 = (const float4*)attn_W;
            float acc = 0.f;
#pragma unroll 4
            for (int c = 0; c < Hn / 128; c++) {
                float4 u = __ldg(u4 + c * 32 + lane);
                float4 d = swd[c * 32 + lane];
                float4 w = __ldg(aw4 + c * 32 + lane);
                acc = fmaf(tanhf(u.x + d.x), w.x, acc);
                acc = fmaf(tanhf(u.y + d.y), w.y, acc);
                acc = fmaf(tanhf(u.z + d.z), w.z, acc);
                acc = fmaf(tanhf(u.w + d.w), w.w, acc);
            }
#pragma unroll
            for (int off = 16; off > 0; off >>= 1)
                acc += __shfl_down_sync(0xffffffffu, acc, off);
            if (lane == 0) g_scores[t] = acc + __ldg(attn_b);
        } else if (bid < 80 && s > 0) {
            const int o = (bid - 64) * WPB + warp;   // 0..127
            const float4* hg4 = (const float4*)hin;
            const float4* row = (const float4*)(h2o_W + (size_t)o * Hn);
            float acc = 0.f;
#pragma unroll 4
            for (int c = 0; c < Hn / 128; c++) {
                float4 w = __ldg(row + c * 32 + lane);
                float4 hv = __ldcg(hg4 + c * 32 + lane);
                acc = fmaf(w.x, hv.x, acc); acc = fmaf(w.y, hv.y, acc);
                acc = fmaf(w.z, hv.z, acc); acc = fmaf(w.w, hv.w, acc);
            }
#pragma unroll
            for (int off = 16; off > 0; off >>= 1)
                acc += __shfl_down_sync(0xffffffffu, acc, off);
            if (lane == 0) g_logits[o] = acc + __ldg(h2o_b + o);
        }
        gen++; gbar(g_arr_dec, &g_rel_dec, gen);

        // ---- Phase C: softmax + ctx partials (0..127) | attns out (129)
        //               | prev-step log_softmax + argmax (128, s>0) ----
        if (bid < 128 || bid == 129) {
            float v0 = __ldcg(g_scores + tid);
            float v1 = __ldcg(g_scores + tid + 256);
            float m = fmaxf(v0, v1);
#pragma unroll
            for (int off = 16; off > 0; off >>= 1)
                m = fmaxf(m, __shfl_xor_sync(0xffffffffu, m, off));
            if (lane == 0) s_red[warp] = m;
            __syncthreads();
            float mx = s_red[0];
#pragma unroll
            for (int w = 1; w < WPB; w++) mx = fmaxf(mx, s_red[w]);
            __syncthreads();
            float e0 = expf(v0 - mx), e1 = expf(v1 - mx);
            float sum = e0 + e1;
#pragma unroll
            for (int off = 16; off > 0; off >>= 1)
                sum += __shfl_xor_sync(0xffffffffu, sum, off);
            if (lane == 0) s_red[warp] = sum;
            __syncthreads();
            float tot = 0.f;
#pragma unroll
            for (int w = 0; w < WPB; w++) tot += s_red[w];
            float inv = 1.0f / tot;
            sbuf[tid] = e0 * inv;
            sbuf[tid + 256] = e1 * inv;
            __syncthreads();
            if (bid == 129) {
                d_out[DSTEP * OUTn + (size_t)s * Tn + tid] = sbuf[tid];
                d_out[DSTEP * OUTn + (size_t)s * Tn + tid + 256] = sbuf[tid + 256];
            } else {
                const int chunk = bid >> 3;              // 0..15
                const int jj = (bid & 7) * 256 + tid;
                const int t0 = chunk * 32;
                float acc = 0.f;
#pragma unroll
                for (int tt = 0; tt < 32; tt++)
                    acc = fmaf(sbuf[t0 + tt],
                               __ldg(g_enc_out + (size_t)(t0 + tt) * Hn + jj), acc);
                g_ctx_part[chunk * Hn + jj] = acc;
            }
        } else if (bid == 128 && s > 0) {
            float lv = (tid < OUTn) ? __ldcg(g_logits + tid) : -INFINITY;
            float v = lv;
            int vi = tid;
#pragma unroll
            for (int off = 16; off > 0; off >>= 1) {
                float ov = __shfl_xor_sync(0xffffffffu, v, off);
                int oi = __shfl_xor_sync(0xffffffffu, vi, off);
                if (ov > v || (ov == v && oi < vi)) { v = ov; vi = oi; }
            }
            if (lane == 0) { s_fval[warp] = v; s_fidx[warp] = vi; }
            __syncthreads();
            if (tid == 0) {
                float mv = s_fval[0]; int mi = s_fidx[0];
#pragma unroll
                for (int w = 1; w < WPB; w++)
                    if (s_fval[w] > mv || (s_fval[w] == mv && s_fidx[w] < mi)) {
                        mv = s_fval[w]; mi = s_fidx[w];
                    }
                s_mx = mv; s_am = mi;
            }
            __syncthreads();
            float mx = s_mx;
            float e = (tid < OUTn) ? expf(lv - mx) : 0.f;
            float sum = e;
#pragma unroll
            for (int off = 16; off > 0; off >>= 1)
                sum += __shfl_xor_sync(0xffffffffu, sum, off);
            if (lane == 0) s_fval[warp] = sum;
            __syncthreads();
            if (tid == 0) {
                float tot = 0.f;
#pragma unroll
                for (int w = 0; w < WPB; w++) tot += s_fval[w];
                s_lse = logf(tot);
                g_idx = s_am;
            }
            __syncthreads();
            if (tid < OUTn)
                d_out[(size_t)(s - 1) * OUTn + tid] = lv - mx - s_lse;
        }
        gen++; gbar(g_arr_dec, &g_rel_dec, gen);

        // ---- Phase D: reduce ctx partials + build din (blocks 0..7) ----
        if (bid < 8) {
            const int jj = bid * 256 + tid;
            float acc = 0.f;
#pragma unroll
            for (int p = 0; p < 16; p++)
                acc += __ldcg(g_ctx_part + p * Hn + jj);
            g_din[Hn + jj] = acc;
            int idx = __ldcg(&g_idx);
            float e = __ldg(o2h_b + jj);
            if (idx >= 0) e += __ldg(o2h_W + (size_t)jj * OUTn + idx);
            g_din[jj] = e;
        }
        gen++; gbar(g_arr_dec, &g_rel_dec, gen);

        // ---- Phase E: decoder GRU (bf16 weights, L2-resident) ----
        {
            float* sdin = sbuf;
            float* shh = sbuf + DINn;
            float4* sdin4 = (float4*)sdin;
            float4* shh4 = (float4*)shh;
            const float4* dg4 = (const float4*)g_din;
            const float4* hg4 = (const float4*)hin;
#pragma unroll
            for (int i = tid; i < DINn / 4; i += NTHR) sdin4[i] = __ldcg(dg4 + i);
#pragma unroll
            for (int i = tid; i < Hn / 4; i += NTHR) shh4[i] = __ldcg(hg4 + i);
            __syncthreads();

            const uint4* ir  = (const uint4*)g_decWih_bf + (size_t)j * (DINn / 8);
            const uint4* iz  = (const uint4*)g_decWih_bf + (size_t)(Hn + j) * (DINn / 8);
            const uint4* in_ = (const uint4*)g_decWih_bf + (size_t)(2 * Hn + j) * (DINn / 8);
            const uint4* hr  = (const uint4*)g_decWhh_bf + (size_t)j * (Hn / 8);
            const uint4* hz  = (const uint4*)g_decWhh_bf + (size_t)(Hn + j) * (Hn / 8);
            const uint4* hn  = (const uint4*)g_decWhh_bf + (size_t)(2 * Hn + j) * (Hn / 8);

            float a_r = 0.f, a_z = 0.f, a_in = 0.f, a_hn = 0.f;
#pragma unroll 4
            for (int c = 0; c < 16; c++) {
                const int idx = c * 32 + lane;
                float4 dA = sdin4[2 * idx];
                float4 dB = sdin4[2 * idx + 1];
                uint4 u0 = __ldg(ir + idx);
                uint4 u1 = __ldg(iz + idx);
                uint4 u2 = __ldg(in_ + idx);
                a_r  = fmaf(blo(u0.x), dA.x, a_r);  a_r  = fmaf(bhi(u0.x), dA.y, a_r);
                a_r  = fmaf(blo(u0.y), dA.z, a_r);  a_r  = fmaf(bhi(u0.y), dA.w, a_r);
                a_r  = fmaf(blo(u0.z), dB.x, a_r);  a_r  = fmaf(bhi(u0.z), dB.y, a_r);
                a_r  = fmaf(blo(u0.w), dB.z, a_r);  a_r  = fmaf(bhi(u0.w), dB.w, a_r);
                a_z  = fmaf(blo(u1.x), dA.x, a_z);  a_z  = fmaf(bhi(u1.x), dA.y, a_z);
                a_z  = fmaf(blo(u1.y), dA.z, a_z);  a_z  = fmaf(bhi(u1.y), dA.w, a_z);
                a_z  = fmaf(blo(u1.z), dB.x, a_z);  a_z  = fmaf(bhi(u1.z), dB.y, a_z);
                a_z  = fmaf(blo(u1.w), dB.z, a_z);  a_z  = fmaf(bhi(u1.w), dB.w, a_z);
                a_in = fmaf(blo(u2.x), dA.x, a_in); a_in = fmaf(bhi(u2.x), dA.y, a_in);
                a_in = fmaf(blo(u2.y), dA.z, a_in); a_in = fmaf(bhi(u2.y), dA.w, a_in);
                a_in = fmaf(blo(u2.z), dB.x, a_in); a_in = fmaf(bhi(u2.z), dB.y, a_in);
                a_in = fmaf(blo(u2.w), dB.z, a_in); a_in = fmaf(bhi(u2.w), dB.w, a_in);
            }
#pragma unroll 4
            for (int c = 0; c < 8; c++) {
                const int idx = c * 32 + lane;
                float4 hA = shh4[2 * idx];
                float4 hB = shh4[2 * idx + 1];
                uint4 u0 = __ldg(hr + idx);
                uint4 u1 = __ldg(hz + idx);
                uint4 u2 = __ldg(hn + idx);
                a_r  = fmaf(blo(u0.x), hA.x, a_r);  a_r  = fmaf(bhi(u0.x), hA.y, a_r);
                a_r  = fmaf(blo(u0.y), hA.z, a_r);  a_r  = fmaf(bhi(u0.y), hA.w, a_r);
                a_r  = fmaf(blo(u0.z), hB.x, a_r);  a_r  = fmaf(bhi(u0.z), hB.y, a_r);
                a_r  = fmaf(blo(u0.w), hB.z, a_r);  a_r  = fmaf(bhi(u0.w), hB.w, a_r);
                a_z  = fmaf(blo(u1.x), hA.x, a_z);  a_z  = fmaf(bhi(u1.x), hA.y, a_z);
                a_z  = fmaf(blo(u1.y), hA.z, a_z);  a_z  = fmaf(bhi(u1.y), hA.w, a_z);
                a_z  = fmaf(blo(u1.z), hB.x, a_z);  a_z  = fmaf(bhi(u1.z), hB.y, a_z);
                a_z  = fmaf(blo(u1.w), hB.z, a_z);  a_z  = fmaf(bhi(u1.w), hB.w, a_z);
                a_hn = fmaf(blo(u2.x), hA.x, a_hn); a_hn = fmaf(bhi(u2.x), hA.y, a_hn);
                a_hn = fmaf(blo(u2.y), hA.z, a_hn); a_hn = fmaf(bhi(u2.y), hA.w, a_hn);
                a_hn = fmaf(blo(u2.z), hB.x, a_hn); a_hn = fmaf(bhi(u2.z), hB.y, a_hn);
                a_hn = fmaf(blo(u2.w), hB.z, a_hn); a_hn = fmaf(bhi(u2.w), hB.w, a_hn);
            }
#pragma unroll
            for (int off = 16; off > 0; off >>= 1) {
                a_r  += __shfl_down_sync(0xffffffffu, a_r,  off);
                a_z  += __shfl_down_sync(0xffffffffu, a_z,  off);
                a_in += __shfl_down_sync(0xffffffffu, a_in, off);
                a_hn += __shfl_down_sync(0xffffffffu, a_hn, off);
            }
            if (lane == 0) {
                float r = sigmoidf_acc(a_r + __ldg(dec_bih + j) + __ldg(dec_bhh + j));
                float z = sigmoidf_acc(a_z + __ldg(dec_bih + Hn + j) + __ldg(dec_bhh + Hn + j));
                float n = tanhf(a_in + __ldg(dec_bih + 2 * Hn + j)
                                + r * (a_hn + __ldg(dec_bhh + 2 * Hn + j)));
                g_h[(s + 1) & 1][j] = (1.0f - z) * n + z * shh[j];
            }
        }
        gen++; gbar(g_arr_dec, &g_rel_dec, gen);
    }

    // ---- tail: logits + log_softmax for output row DSTEP-1 ----
    if (bid < 16) {
        const int o = bid * WPB + warp;
        const float4* hg4 = (const float4*)g_h[DSTEP & 1];
        const float4* row = (const float4*)(h2o_W + (size_t)o * Hn);
        float acc = 0.f;
#pragma unroll 4
        for (int c = 0; c < Hn / 128; c++) {
            float4 w = __ldg(row + c * 32 + lane);
            float4 hv = __ldcg(hg4 + c * 32 + lane);
            acc = fmaf(w.x, hv.x, acc); acc = fmaf(w.y, hv.y, acc);
            acc = fmaf(w.z, hv.z, acc); acc = fmaf(w.w, hv.w, acc);
        }
#pragma unroll
        for (int off = 16; off > 0; off >>= 1)
            acc += __shfl_down_sync(0xffffffffu, acc, off);
        if (lane == 0) g_logits[o] = acc + __ldg(h2o_b + o);
    }
    gen++; gbar(g_arr_dec, &g_rel_dec, gen);

    if (bid == 0) {
        float lv = (tid < OUTn) ? __ldcg(g_logits + tid) : -INFINITY;
        float v = lv;
#pragma unroll
        for (int off = 16; off > 0; off >>= 1)
            v = fmaxf(v, __shfl_xor_sync(0xffffffffu, v, off));
        if (lane == 0) s_fval[warp] = v;
        __syncthreads();
        if (tid == 0) {
            float mv = s_fval[0];
#pragma unroll
            for (int w = 1; w < WPB; w++) mv = fmaxf(mv, s_fval[w]);
            s_mx = mv;
        }
        __syncthreads();
        float mx = s_mx;
        float e = (tid < OUTn) ? expf(lv - mx) : 0.f;
        float sum = e;
#pragma unroll
        for (int off = 16; off > 0; off >>= 1)
            sum += __shfl_xor_sync(0xffffffffu, sum, off);
        if (lane == 0) s_fval[warp] = sum;
        __syncthreads();
        if (tid == 0) {
            float tot = 0.f;
#pragma unroll
            for (int w = 0; w < WPB; w++) tot += s_fval[w];
            s_lse = logf(tot);
        }
        __syncthreads();
        if (tid < OUTn)
            d_out[(size_t)(DSTEP - 1) * OUTn + tid] = lv - mx - s_lse;
    }
}

// ---------------- launch ----------------
extern "C" void kernel_launch(void* const* d_in, const int* in_sizes, int n_in,
                              void* d_out, int out_size)
{
    const float* x        = (const float*)d_in[0];
    const float* enc_Wih  = (const float*)d_in[1];
    const float* enc_Whh  = (const float*)d_in[2];
    const float* enc_bih  = (const float*)d_in[3];
    const float* enc_bhh  = (const float*)d_in[4];
    const float* dec_Wih  = (const float*)d_in[5];
    const float* dec_Whh  = (const float*)d_in[6];
    const float* dec_bih  = (const float*)d_in[7];
    const float* dec_bhh  = (const float*)d_in[8];
    const float* h2o_W    = (const float*)d_in[9];
    const float* h2o_b    = (const float*)d_in[10];
    const float* U_W      = (const float*)d_in[11];
    const float* U_b      = (const float*)d_in[12];
    const float* W_W      = (const float*)d_in[13];
    const float* W_b      = (const float*)d_in[14];
    const float* attn_W   = (const float*)d_in[15];
    const float* attn_b   = (const float*)d_in[16];
    const float* o2h_W    = (const float*)d_in[17];
    const float* o2h_b    = (const float*)d_in[18];
    float* out = (float*)d_out;
    (void)in_sizes; (void)n_in; (void)out_size;

    float *gi_ptr, *enc_out_ptr, *U_ptr;
    __nv_bfloat16 *wih_bf, *whh_bf, *ww_bf;
    cudaGetSymbolAddress((void**)&gi_ptr, g_enc_gi);
    cudaGetSymbolAddress((void**)&enc_out_ptr, g_enc_out);
    cudaGetSymbolAddress((void**)&U_ptr, g_U);
    cudaGetSymbolAddress((void**)&wih_bf, g_decWih_bf);
    cudaGetSymbolAddress((void**)&whh_bf, g_decWhh_bf);
    cudaGetSymbolAddress((void**)&ww_bf, g_WW_bf);

    init_kernel<<<8, 256>>>();

    // convert decoder-side weights to bf16
    f2bf_kernel<<<2048, 256>>>(dec_Wih, wih_bf, G3n * DINn / 2);
    f2bf_kernel<<<2048, 256>>>(dec_Whh, whh_bf, G3n * Hn / 2);
    f2bf_kernel<<<1024, 256>>>(W_W, ww_bf, Hn * Hn / 2);

    // gi = x @ enc_Wih^T + bih
    gemm_nt_bias<<<dim3(G3n / 64, Tn / 64), 256>>>(x, enc_Wih, enc_bih, gi_ptr,
                                                   Tn, G3n, INn);
    // encoder (bf16 weights resident in smem)
    const int enc_smem = WPB * 3 * 1024 * 4 + Hn * 4;   // 96KB + 8KB
    cudaFuncSetAttribute(enc_persistent,
                         cudaFuncAttributeMaxDynamicSharedMemorySize, enc_smem);
    enc_persistent<<<NBLK, NTHR, enc_smem>>>(enc_Whh, enc_bhh);

    // U = enc_out @ U_W^T + U_b
    gemm_nt_bias<<<dim3(Hn / 64, Tn / 64), 256>>>(enc_out_ptr, U_W, U_b, U_ptr,
                                                  Tn, Hn, Hn);
    // decoder
    dec_persistent<<<NBLK, NTHR>>>(dec_bih, dec_bhh, h2o_W, h2o_b, W_b,
                                   attn_W, attn_b, o2h_W, o2h_b, out);
}

// round 5
// speedup vs baseline: 1.7856x; 1.2054x over previous
#include <cuda_runtime.h>
#include <cuda_bf16.h>
#include <math.h>

#define Hn    2048
#define Tn    512
#define INn   128
#define OUTn  128
#define G3n   6144
#define DSTEP 64
#define DINn  4096

#define NBLK  148
#define ETHR  256    // encoder threads (8 warps, 7 active)
#define DTHR  512    // decoder threads (16 warps)

// ---------------- device scratch ----------------
__device__ float g_enc_gi[Tn * G3n];
__device__ float g_enc_out[Tn * Hn];
__device__ float g_U[Tn * Hn];
__device__ float g_h[2][Hn];
__device__ float g_Wd[Hn];
__device__ float g_scores[Tn];
__device__ float g_ctx_part[32 * Hn];
__device__ float g_din[DINn];
__device__ float g_logits[OUTn];
__device__ int   g_idx;

__device__ __nv_bfloat16 g_decWih_bf[G3n * DINn];
__device__ __nv_bfloat16 g_decWhh_bf[G3n * Hn];
__device__ __nv_bfloat16 g_WW_bf[Hn * Hn];

__device__ unsigned g_arr_enc[NBLK];
__device__ unsigned g_rel_enc;
__device__ unsigned g_arr_dec[NBLK];
__device__ unsigned g_rel_dec;

// ---------------- acquire/release helpers ----------------
__device__ __forceinline__ void st_rel(unsigned* p, unsigned v) {
    asm volatile("st.global.release.gpu.u32 [%0], %1;" :: "l"(p), "r"(v) : "memory");
}
__device__ __forceinline__ unsigned ld_acq(unsigned* p) {
    unsigned v;
    asm volatile("ld.global.acquire.gpu.u32 %0, [%1];" : "=r"(v) : "l"(p) : "memory");
    return v;
}

// flag barrier over NBLK blocks, release/acquire ordering
__device__ __forceinline__ void gbar(unsigned* arr, unsigned* rel, unsigned gen) {
    __syncthreads();
    if (blockIdx.x == 0) {
        if (threadIdx.x >= 1 && threadIdx.x < NBLK)
            while (ld_acq(&arr[threadIdx.x]) < gen) { }
        __syncthreads();
        if (threadIdx.x == 0) st_rel(rel, gen);
    } else {
        if (threadIdx.x == 0) {
            st_rel(&arr[blockIdx.x], gen);
            while (ld_acq(rel) < gen) { }
        }
        __syncthreads();
    }
}

__device__ __forceinline__ float sigmoidf_acc(float x) {
    return 1.0f / (1.0f + expf(-x));
}
__device__ __forceinline__ float blo(unsigned u) { return __int_as_float(u << 16); }
__device__ __forceinline__ float bhi(unsigned u) { return __int_as_float(u & 0xffff0000u); }

#define ACC8(acc, u, hA, hB) \
    acc = fmaf(blo(u.x), hA.x, acc); acc = fmaf(bhi(u.x), hA.y, acc); \
    acc = fmaf(blo(u.y), hA.z, acc); acc = fmaf(bhi(u.y), hA.w, acc); \
    acc = fmaf(blo(u.z), hB.x, acc); acc = fmaf(bhi(u.z), hB.y, acc); \
    acc = fmaf(blo(u.w), hB.z, acc); acc = fmaf(bhi(u.w), hB.w, acc);

// ---------------- init ----------------
__global__ void init_kernel() {
    int i = blockIdx.x * blockDim.x + threadIdx.x;
    if (i < Hn) g_h[0][i] = 0.0f;
    if (i < NBLK) { g_arr_enc[i] = 0u; g_arr_dec[i] = 0u; }
    if (i == 0) { g_rel_enc = 0u; g_rel_dec = 0u; g_idx = -1; }
}

// ---------------- fp32 -> bf16 ----------------
__global__ void f2bf_kernel(const float* __restrict__ in,
                            __nv_bfloat16* __restrict__ out, int n_pairs) {
    int stride = gridDim.x * blockDim.x;
    const float2* in2 = (const float2*)in;
    __nv_bfloat162* out2 = (__nv_bfloat162*)out;
    for (int i = blockIdx.x * blockDim.x + threadIdx.x; i < n_pairs; i += stride)
        out2[i] = __float22bfloat162_rn(in2[i]);
}

// ---------------- tiled GEMM: C[M,N] = A[M,K] @ B[N,K]^T + bias ----------------
__global__ void __launch_bounds__(256) gemm_nt_bias(
    const float* __restrict__ A, const float* __restrict__ B,
    const float* __restrict__ bias, float* __restrict__ C,
    int M, int N, int K)
{
    __shared__ float As[16][68];
    __shared__ float Bs[16][68];
    const int m0 = blockIdx.y * 64;
    const int n0 = blockIdx.x * 64;
    const int tid = threadIdx.x;
    const int tx = tid & 15;
    const int ty = tid >> 4;
    float c[4][4] = {};

    for (int k0 = 0; k0 < K; k0 += 16) {
#pragma unroll
        for (int i = 0; i < 4; i++) {
            int idx = tid + i * 256;
            int kk = idx & 15;
            int mm = idx >> 4;
            As[kk][mm] = A[(size_t)(m0 + mm) * K + k0 + kk];
            Bs[kk][mm] = B[(size_t)(n0 + mm) * K + k0 + kk];
        }
        __syncthreads();
#pragma unroll
        for (int kk = 0; kk < 16; kk++) {
            float4 a4 = *(const float4*)&As[kk][ty * 4];
            float4 b4 = *(const float4*)&Bs[kk][tx * 4];
            float av[4] = {a4.x, a4.y, a4.z, a4.w};
            float bv[4] = {b4.x, b4.y, b4.z, b4.w};
#pragma unroll
            for (int i = 0; i < 4; i++)
#pragma unroll
                for (int j = 0; j < 4; j++)
                    c[i][j] = fmaf(av[i], bv[j], c[i][j]);
        }
        __syncthreads();
    }
#pragma unroll
    for (int i = 0; i < 4; i++) {
        int m = m0 + ty * 4 + i;
#pragma unroll
        for (int j = 0; j < 4; j++) {
            int n = n0 + tx * 4 + j;
            C[(size_t)m * N + n] = c[i][j] + bias[n];
        }
    }
}

// ---------------- persistent encoder: 148 blocks, 2 j per warp, smem bf16 weights --
// Dynamic smem: [0, 168KB) weights: warp w, row r (6 rows: g*2 + jj) * 1024 u32
//               [168KB, 176KB) fp32 h staging (2048 floats)
#define ENC_WSMEM (7 * 6 * 1024)           // u32 words
#define ENC_SMEM  (ENC_WSMEM * 4 + Hn * 4) // bytes

__global__ void __launch_bounds__(ETHR, 1) enc_persistent(
    const float* __restrict__ Whh, const float* __restrict__ bhh)
{
    extern __shared__ char smem_raw[];
    unsigned* sw = (unsigned*)smem_raw;
    float* shh = (float*)(smem_raw + ENC_WSMEM * 4);
    float4* shh4 = (float4*)shh;
    const uint4* sw4 = (const uint4*)sw;

    const int warp = threadIdx.x >> 5;
    const int lane = threadIdx.x & 31;
    const int tid = threadIdx.x;
    const int j0 = (blockIdx.x * 7 + warp) * 2;
    const bool active = (warp < 7) && (j0 < Hn);

    float bR0 = 0, bR1 = 0, bZ0 = 0, bZ1 = 0, bN0 = 0, bN1 = 0;
    if (active) {
        // rows: r = g*2 + jj  (g: 0=r,1=z,2=n)
#pragma unroll
        for (int r = 0; r < 6; r++) {
            const int g = r >> 1, jj = r & 1;
            const float2* src = (const float2*)(Whh + ((size_t)g * Hn + j0 + jj) * Hn);
            unsigned* dst = sw + (warp * 6 + r) * 1024;
            for (int i = lane; i < 1024; i += 32) {
                __nv_bfloat162 b2 = __float22bfloat162_rn(__ldg(src + i));
                dst[i] = *(unsigned*)&b2;
            }
        }
        bR0 = bhh[j0];          bR1 = bhh[j0 + 1];
        bZ0 = bhh[Hn + j0];     bZ1 = bhh[Hn + j0 + 1];
        bN0 = bhh[2 * Hn + j0]; bN1 = bhh[2 * Hn + j0 + 1];
    }
    unsigned gen = 0;
    __syncthreads();

    for (int t = 0; t < Tn; t++) {
        // prefetch gi (independent of h)
        float giR0 = 0, giR1 = 0, giZ0 = 0, giZ1 = 0, giN0 = 0, giN1 = 0;
        if (active && lane == 0) {
            const float* gi = g_enc_gi + (size_t)t * G3n;
            giR0 = __ldcs(gi + j0);          giR1 = __ldcs(gi + j0 + 1);
            giZ0 = __ldcs(gi + Hn + j0);     giZ1 = __ldcs(gi + Hn + j0 + 1);
            giN0 = __ldcs(gi + 2 * Hn + j0); giN1 = __ldcs(gi + 2 * Hn + j0 + 1);
        }
        // stage h
        const float4* hg4 = (const float4*)g_h[t & 1];
#pragma unroll
        for (int i = tid; i < Hn / 4; i += ETHR) shh4[i] = __ldcg(hg4 + i);
        __syncthreads();

        float aR0 = 0, aR1 = 0, aZ0 = 0, aZ1 = 0, aN0 = 0, aN1 = 0;
        if (active) {
            const uint4* w = sw4 + (size_t)warp * 6 * 256;
#pragma unroll
            for (int c = 0; c < 8; c++) {
                const int idx = c * 32 + lane;
                float4 hA = shh4[2 * idx];
                float4 hB = shh4[2 * idx + 1];
                uint4 uR0 = w[0 * 256 + idx];
                uint4 uR1 = w[1 * 256 + idx];
                uint4 uZ0 = w[2 * 256 + idx];
                uint4 uZ1 = w[3 * 256 + idx];
                uint4 uN0 = w[4 * 256 + idx];
                uint4 uN1 = w[5 * 256 + idx];
                ACC8(aR0, uR0, hA, hB)
                ACC8(aR1, uR1, hA, hB)
                ACC8(aZ0, uZ0, hA, hB)
                ACC8(aZ1, uZ1, hA, hB)
                ACC8(aN0, uN0, hA, hB)
                ACC8(aN1, uN1, hA, hB)
            }
#pragma unroll
            for (int off = 16; off > 0; off >>= 1) {
                aR0 += __shfl_down_sync(0xffffffffu, aR0, off);
                aR1 += __shfl_down_sync(0xffffffffu, aR1, off);
                aZ0 += __shfl_down_sync(0xffffffffu, aZ0, off);
                aZ1 += __shfl_down_sync(0xffffffffu, aZ1, off);
                aN0 += __shfl_down_sync(0xffffffffu, aN0, off);
                aN1 += __shfl_down_sync(0xffffffffu, aN1, off);
            }
            if (lane == 0) {
                float* hout = g_h[(t + 1) & 1];
                float* eout = g_enc_out + (size_t)t * Hn;
                float r0 = sigmoidf_acc(giR0 + aR0 + bR0);
                float z0 = sigmoidf_acc(giZ0 + aZ0 + bZ0);
                float n0 = tanhf(giN0 + r0 * (aN0 + bN0));
                float h0 = (1.0f - z0) * n0 + z0 * shh[j0];
                hout[j0] = h0; eout[j0] = h0;
                float r1 = sigmoidf_acc(giR1 + aR1 + bR1);
                float z1 = sigmoidf_acc(giZ1 + aZ1 + bZ1);
                float n1 = tanhf(giN1 + r1 * (aN1 + bN1));
                float h1 = (1.0f - z1) * n1 + z1 * shh[j0 + 1];
                hout[j0 + 1] = h1; eout[j0 + 1] = h1;
            }
        }
        gen++;
        gbar(g_arr_enc, &g_rel_enc, gen);
    }
}

// ---------------- persistent decoder: 148 blocks x 512 thr ----------------
__global__ void __launch_bounds__(DTHR, 1) dec_persistent(
    const float* __restrict__ dec_bih, const float* __restrict__ dec_bhh,
    const float* __restrict__ h2o_W, const float* __restrict__ h2o_b,
    const float* __restrict__ W_b,
    const float* __restrict__ attn_W, const float* __restrict__ attn_b,
    const float* __restrict__ o2h_W, const float* __restrict__ o2h_b,
    float* __restrict__ d_out)
{
    __shared__ float sbuf[DINn + Hn];
    __shared__ float s_red[16];
    __shared__ float s_fval[16];
    __shared__ int   s_fidx[16];
    __shared__ float s_mx, s_lse;
    __shared__ int   s_am;

    const int warp = threadIdx.x >> 5;
    const int lane = threadIdx.x & 31;
    const int tid = threadIdx.x;
    const int bid = blockIdx.x;
    unsigned gen = 0;

    for (int s = 0; s < DSTEP; s++) {
        const float* hin = g_h[s & 1];

        // ---- Phase A: Wd = h @ W_W^T + W_b (14 j per block) ----
        {
            float4* sh4 = (float4*)sbuf;
            const float4* hg4 = (const float4*)hin;
#pragma unroll
            for (int i = tid; i < Hn / 4; i += DTHR) sh4[i] = __ldcg(hg4 + i);
            __syncthreads();
            const int j = bid * 14 + warp;
            if (warp < 14 && j < Hn) {
                const uint4* row = (const uint4*)g_WW_bf + (size_t)j * (Hn / 8);
                float acc = 0.f;
#pragma unroll
                for (int c = 0; c < 8; c++) {
                    const int idx = c * 32 + lane;
                    float4 hA = sh4[2 * idx];
                    float4 hB = sh4[2 * idx + 1];
                    uint4 u = __ldg(row + idx);
                    ACC8(acc, u, hA, hB)
                }
#pragma unroll
                for (int off = 16; off > 0; off >>= 1)
                    acc += __shfl_down_sync(0xffffffffu, acc, off);
                if (lane == 0) g_Wd[j] = acc + __ldg(W_b + j);
            }
        }
        gen++; gbar(g_arr_dec, &g_rel_dec, gen);

        // ---- Phase B: scores (blocks 0..127, 4 warps) | logits h_s (128..135, s>0) --
        if (bid < 128) {
            float4* swd = (float4*)sbuf;
            const float4* wd4 = (const float4*)g_Wd;
#pragma unroll
            for (int i = tid; i < Hn / 4; i += DTHR) swd[i] = __ldcg(wd4 + i);
            __syncthreads();
            if (warp < 4) {
                const int t = bid * 4 + warp;   // 0..511
                const float4* u4 = (const float4*)(g_U + (size_t)t * Hn);
                const float4* aw4 = (const float4*)attn_W;
                float acc = 0.f;
#pragma unroll 4
                for (int c = 0; c < Hn / 128; c++) {
                    float4 u = __ldg(u4 + c * 32 + lane);
                    float4 d = swd[c * 32 + lane];
                    float4 w = __ldg(aw4 + c * 32 + lane);
                    acc = fmaf(tanhf(u.x + d.x), w.x, acc);
                    acc = fmaf(tanhf(u.y + d.y), w.y, acc);
                    acc = fmaf(tanhf(u.z + d.z), w.z, acc);
                    acc = fmaf(tanhf(u.w + d.w), w.w, acc);
                }
#pragma unroll
                for (int off = 16; off > 0; off >>= 1)
                    acc += __shfl_down_sync(0xffffffffu, acc, off);
                if (lane == 0) g_scores[t] = acc + __ldg(attn_b);
            }
        } else if (bid < 136 && s > 0) {
            const int o = (bid - 128) * 16 + warp;   // 0..127
            const float4* hg4 = (const float4*)hin;
            const float4* row = (const float4*)(h2o_W + (size_t)o * Hn);
            float acc = 0.f;
#pragma unroll 4
            for (int c = 0; c < Hn / 128; c++) {
                float4 w = __ldg(row + c * 32 + lane);
                float4 hv = __ldcg(hg4 + c * 32 + lane);
                acc = fmaf(w.x, hv.x, acc); acc = fmaf(w.y, hv.y, acc);
                acc = fmaf(w.z, hv.z, acc); acc = fmaf(w.w, hv.w, acc);
            }
#pragma unroll
            for (int off = 16; off > 0; off >>= 1)
                acc += __shfl_down_sync(0xffffffffu, acc, off);
            if (lane == 0) g_logits[o] = acc + __ldg(h2o_b + o);
        }
        gen++; gbar(g_arr_dec, &g_rel_dec, gen);

        // ---- Phase C: softmax + ctx partials (0..127) | attns (128) | argmax (129) --
        if (bid < 128 || bid == 128) { }
        if (bid <= 128) {
            // local softmax over 512 scores (one score per thread)
            float v = __ldcg(g_scores + tid);
            float m = v;
#pragma unroll
            for (int off = 16; off > 0; off >>= 1)
                m = fmaxf(m, __shfl_xor_sync(0xffffffffu, m, off));
            if (lane == 0) s_red[warp] = m;
            __syncthreads();
            float mx = s_red[0];
#pragma unroll
            for (int w = 1; w < 16; w++) mx = fmaxf(mx, s_red[w]);
            __syncthreads();
            float e = expf(v - mx);
            float sum = e;
#pragma unroll
            for (int off = 16; off > 0; off >>= 1)
                sum += __shfl_xor_sync(0xffffffffu, sum, off);
            if (lane == 0) s_red[warp] = sum;
            __syncthreads();
            float tot = 0.f;
#pragma unroll
            for (int w = 0; w < 16; w++) tot += s_red[w];
            float aw = e / tot;
            sbuf[tid] = aw;
            __syncthreads();
            if (bid == 128) {
                d_out[DSTEP * OUTn + (size_t)s * Tn + tid] = aw;
            } else {
                const int chunk = bid >> 2;              // 0..31 (16 t each)
                const int jj = (bid & 3) * 512 + tid;    // 0..2047
                const int t0 = chunk * 16;
                float acc = 0.f;
#pragma unroll
                for (int tt = 0; tt < 16; tt++)
                    acc = fmaf(sbuf[t0 + tt],
                               __ldg(g_enc_out + (size_t)(t0 + tt) * Hn + jj), acc);
                g_ctx_part[chunk * Hn + jj] = acc;
            }
        } else if (bid == 129 && s > 0) {
            float lv = (tid < OUTn) ? __ldcg(g_logits + tid) : -INFINITY;
            float v = lv;
            int vi = tid;
#pragma unroll
            for (int off = 16; off > 0; off >>= 1) {
                float ov = __shfl_xor_sync(0xffffffffu, v, off);
                int oi = __shfl_xor_sync(0xffffffffu, vi, off);
                if (ov > v || (ov == v && oi < vi)) { v = ov; vi = oi; }
            }
            if (lane == 0) { s_fval[warp] = v; s_fidx[warp] = vi; }
            __syncthreads();
            if (tid == 0) {
                float mv = s_fval[0]; int mi = s_fidx[0];
#pragma unroll
                for (int w = 1; w < 16; w++)
                    if (s_fval[w] > mv || (s_fval[w] == mv && s_fidx[w] < mi)) {
                        mv = s_fval[w]; mi = s_fidx[w];
                    }
                s_mx = mv; s_am = mi;
            }
            __syncthreads();
            float mx = s_mx;
            float e = (tid < OUTn) ? expf(lv - mx) : 0.f;
            float sum = e;
#pragma unroll
            for (int off = 16; off > 0; off >>= 1)
                sum += __shfl_xor_sync(0xffffffffu, sum, off);
            if (lane == 0) s_fval[warp] = sum;
            __syncthreads();
            if (tid == 0) {
                float tot = 0.f;
#pragma unroll
                for (int w = 0; w < 16; w++) tot += s_fval[w];
                s_lse = logf(tot);
                g_idx = s_am;
            }
            __syncthreads();
            if (tid < OUTn)
                d_out[(size_t)(s - 1) * OUTn + tid] = lv - mx - s_lse;
        }
        gen++; gbar(g_arr_dec, &g_rel_dec, gen);

        // ---- Phase D: reduce ctx partials + build din (blocks 0..3) ----
        if (bid < 4) {
            const int jj = bid * 512 + tid;
            float acc = 0.f;
#pragma unroll
            for (int p = 0; p < 32; p++)
                acc += __ldcg(g_ctx_part + p * Hn + jj);
            g_din[Hn + jj] = acc;
            int idx = __ldcg(&g_idx);
            float e = __ldg(o2h_b + jj);
            if (idx >= 0) e += __ldg(o2h_W + (size_t)jj * OUTn + idx);
            g_din[jj] = e;
        }
        gen++; gbar(g_arr_dec, &g_rel_dec, gen);

        // ---- Phase E: decoder GRU (14 j per block, bf16 weights) ----
        {
            float* sdin = sbuf;
            float* shh = sbuf + DINn;
            float4* sdin4 = (float4*)sdin;
            float4* shh4 = (float4*)shh;
            const float4* dg4 = (const float4*)g_din;
            const float4* hg4 = (const float4*)hin;
#pragma unroll
            for (int i = tid; i < DINn / 4; i += DTHR) sdin4[i] = __ldcg(dg4 + i);
#pragma unroll
            for (int i = tid; i < Hn / 4; i += DTHR) shh4[i] = __ldcg(hg4 + i);
            __syncthreads();

            const int j = bid * 14 + warp;
            if (warp < 14 && j < Hn) {
                const uint4* ir  = (const uint4*)g_decWih_bf + (size_t)j * (DINn / 8);
                const uint4* iz  = (const uint4*)g_decWih_bf + (size_t)(Hn + j) * (DINn / 8);
                const uint4* in_ = (const uint4*)g_decWih_bf + (size_t)(2 * Hn + j) * (DINn / 8);
                const uint4* hr  = (const uint4*)g_decWhh_bf + (size_t)j * (Hn / 8);
                const uint4* hz  = (const uint4*)g_decWhh_bf + (size_t)(Hn + j) * (Hn / 8);
                const uint4* hn  = (const uint4*)g_decWhh_bf + (size_t)(2 * Hn + j) * (Hn / 8);

                float a_r = 0.f, a_z = 0.f, a_in = 0.f, a_hn = 0.f;
#pragma unroll 4
                for (int c = 0; c < 16; c++) {
                    const int idx = c * 32 + lane;
                    float4 dA = sdin4[2 * idx];
                    float4 dB = sdin4[2 * idx + 1];
                    uint4 u0 = __ldg(ir + idx);
                    uint4 u1 = __ldg(iz + idx);
                    uint4 u2 = __ldg(in_ + idx);
                    ACC8(a_r, u0, dA, dB)
                    ACC8(a_z, u1, dA, dB)
                    ACC8(a_in, u2, dA, dB)
                }
#pragma unroll 4
                for (int c = 0; c < 8; c++) {
                    const int idx = c * 32 + lane;
                    float4 hA = shh4[2 * idx];
                    float4 hB = shh4[2 * idx + 1];
                    uint4 u0 = __ldg(hr + idx);
                    uint4 u1 = __ldg(hz + idx);
                    uint4 u2 = __ldg(hn + idx);
                    ACC8(a_r, u0, hA, hB)
                    ACC8(a_z, u1, hA, hB)
                    ACC8(a_hn, u2, hA, hB)
                }
#pragma unroll
                for (int off = 16; off > 0; off >>= 1) {
                    a_r  += __shfl_down_sync(0xffffffffu, a_r,  off);
                    a_z  += __shfl_down_sync(0xffffffffu, a_z,  off);
                    a_in += __shfl_down_sync(0xffffffffu, a_in, off);
                    a_hn += __shfl_down_sync(0xffffffffu, a_hn, off);
                }
                if (lane == 0) {
                    float r = sigmoidf_acc(a_r + __ldg(dec_bih + j) + __ldg(dec_bhh + j));
                    float z = sigmoidf_acc(a_z + __ldg(dec_bih + Hn + j) + __ldg(dec_bhh + Hn + j));
                    float n = tanhf(a_in + __ldg(dec_bih + 2 * Hn + j)
                                    + r * (a_hn + __ldg(dec_bhh + 2 * Hn + j)));
                    g_h[(s + 1) & 1][j] = (1.0f - z) * n + z * shh[j];
                }
            }
        }
        gen++; gbar(g_arr_dec, &g_rel_dec, gen);
    }

    // ---- tail: logits + log_softmax for output row DSTEP-1 ----
    if (bid < 8) {
        const int o = bid * 16 + warp;   // 0..127
        const float4* hg4 = (const float4*)g_h[DSTEP & 1];
        const float4* row = (const float4*)(h2o_W + (size_t)o * Hn);
        float acc = 0.f;
#pragma unroll 4
        for (int c = 0; c < Hn / 128; c++) {
            float4 w = __ldg(row + c * 32 + lane);
            float4 hv = __ldcg(hg4 + c * 32 + lane);
            acc = fmaf(w.x, hv.x, acc); acc = fmaf(w.y, hv.y, acc);
            acc = fmaf(w.z, hv.z, acc); acc = fmaf(w.w, hv.w, acc);
        }
#pragma unroll
        for (int off = 16; off > 0; off >>= 1)
            acc += __shfl_down_sync(0xffffffffu, acc, off);
        if (lane == 0) g_logits[o] = acc + __ldg(h2o_b + o);
    }
    gen++; gbar(g_arr_dec, &g_rel_dec, gen);

    if (bid == 0) {
        float lv = (tid < OUTn) ? __ldcg(g_logits + tid) : -INFINITY;
        float v = lv;
#pragma unroll
        for (int off = 16; off > 0; off >>= 1)
            v = fmaxf(v, __shfl_xor_sync(0xffffffffu, v, off));
        if (lane == 0) s_fval[warp] = v;
        __syncthreads();
        if (tid == 0) {
            float mv = s_fval[0];
#pragma unroll
            for (int w = 1; w < 16; w++) mv = fmaxf(mv, s_fval[w]);
            s_mx = mv;
        }
        __syncthreads();
        float mx = s_mx;
        float e = (tid < OUTn) ? expf(lv - mx) : 0.f;
        float sum = e;
#pragma unroll
        for (int off = 16; off > 0; off >>= 1)
            sum += __shfl_xor_sync(0xffffffffu, sum, off);
        if (lane == 0) s_fval[warp] = sum;
        __syncthreads();
        if (tid == 0) {
            float tot = 0.f;
#pragma unroll
            for (int w = 0; w < 16; w++) tot += s_fval[w];
            s_lse = logf(tot);
        }
        __syncthreads();
        if (tid < OUTn)
            d_out[(size_t)(DSTEP - 1) * OUTn + tid] = lv - mx - s_lse;
    }
}

// ---------------- launch ----------------
extern "C" void kernel_launch(void* const* d_in, const int* in_sizes, int n_in,
                              void* d_out, int out_size)
{
    const float* x        = (const float*)d_in[0];
    const float* enc_Wih  = (const float*)d_in[1];
    const float* enc_Whh  = (const float*)d_in[2];
    const float* enc_bih  = (const float*)d_in[3];
    const float* enc_bhh  = (const float*)d_in[4];
    const float* dec_Wih  = (const float*)d_in[5];
    const float* dec_Whh  = (const float*)d_in[6];
    const float* dec_bih  = (const float*)d_in[7];
    const float* dec_bhh  = (const float*)d_in[8];
    const float* h2o_W    = (const float*)d_in[9];
    const float* h2o_b    = (const float*)d_in[10];
    const float* U_W      = (const float*)d_in[11];
    const float* U_b      = (const float*)d_in[12];
    const float* W_W      = (const float*)d_in[13];
    const float* W_b      = (const float*)d_in[14];
    const float* attn_W   = (const float*)d_in[15];
    const float* attn_b   = (const float*)d_in[16];
    const float* o2h_W    = (const float*)d_in[17];
    const float* o2h_b    = (const float*)d_in[18];
    float* out = (float*)d_out;
    (void)in_sizes; (void)n_in; (void)out_size;

    float *gi_ptr, *enc_out_ptr, *U_ptr;
    __nv_bfloat16 *wih_bf, *whh_bf, *ww_bf;
    cudaGetSymbolAddress((void**)&gi_ptr, g_enc_gi);
    cudaGetSymbolAddress((void**)&enc_out_ptr, g_enc_out);
    cudaGetSymbolAddress((void**)&U_ptr, g_U);
    cudaGetSymbolAddress((void**)&wih_bf, g_decWih_bf);
    cudaGetSymbolAddress((void**)&whh_bf, g_decWhh_bf);
    cudaGetSymbolAddress((void**)&ww_bf, g_WW_bf);

    init_kernel<<<8, 256>>>();

    f2bf_kernel<<<2048, 256>>>(dec_Wih, wih_bf, G3n * DINn / 2);
    f2bf_kernel<<<2048, 256>>>(dec_Whh, whh_bf, G3n * Hn / 2);
    f2bf_kernel<<<1024, 256>>>(W_W, ww_bf, Hn * Hn / 2);

    gemm_nt_bias<<<dim3(G3n / 64, Tn / 64), 256>>>(x, enc_Wih, enc_bih, gi_ptr,
                                                   Tn, G3n, INn);

    cudaFuncSetAttribute(enc_persistent,
                         cudaFuncAttributeMaxDynamicSharedMemorySize, ENC_SMEM);
    enc_persistent<<<NBLK, ETHR, ENC_SMEM>>>(enc_Whh, enc_bhh);

    gemm_nt_bias<<<dim3(Hn / 64, Tn / 64), 256>>>(enc_out_ptr, U_W, U_b, U_ptr,
                                                  Tn, Hn, Hn);

    dec_persistent<<<NBLK, DTHR>>>(dec_bih, dec_bhh, h2o_W, h2o_b, W_b,
                                   attn_W, attn_b, o2h_W, o2h_b, out);
}